// round 12
// baseline (speedup 1.0000x reference)
#include <cuda_runtime.h>
#include <cuda_fp16.h>
#include <cstdint>
#include <cstddef>

// ---------------- problem constants ----------------
#define TOTAL    65536          // B_GRAPHS * N_NODES
#define NGRAPH   16
#define NNODES   4096
#define INCH     256
#define HID      512
#define LN_EPS   1e-5f
#define QK_EPS   1e-6f
#define KBLOCKS  (TOTAL / 8)

// ---------------- GEMM tiling: 128x128 tile, warp 64x32, fp16, BK=64 ----------------
#define BM 128
#define BN 128
#define BK 64
// TR0 slot: 128 rows x 72 halfs (144 B/row) = 18432 B
// TR1 slot: 64 rows x 136 halfs (272 B/row) = 17408 B
#define SLOT_BYTES  18432
#define STAGE_BYTES (2 * SLOT_BYTES)        // 36864
#define NSTAGE 3
#define SMEM_BYTES (NSTAGE * STAGE_BYTES)   // 110592 -> 2 CTAs/SM (216 KB)

// epilogue modes
#define EPI_NONE 0
#define EPI_BIAS 1
#define EPI_ATT  2

// ---------------- scratch (device globals; no allocation) ----------------
__device__ __half g_h  [(size_t)TOTAL * HID];
__device__ __half g_q  [(size_t)TOTAL * HID];
__device__ __half g_k  [(size_t)TOTAL * HID];
__device__ __half g_v  [(size_t)TOTAL * HID];
__device__ __half g_xh [(size_t)TOTAL * INCH];
__device__ __half g_wh [(size_t)(HID * INCH + 6 * HID * HID)];
__device__ __half g_kvsh[(size_t)NGRAPH * HID * HID];
__device__ float  g_t  [(size_t)TOTAL * HID];       // fp32 final layer; fp16 view for intermediates
__device__ float  g_ksp [(size_t)KBLOCKS * HID];
__device__ float  g_ks  [(size_t)NGRAPH * HID];
__device__ float  g_den [(size_t)TOTAL];

// ---------------- helpers ----------------
__device__ __forceinline__ uint32_t smem_to_u32(const void* p) {
    uint32_t a;
    asm("{ .reg .u64 t; cvta.to.shared.u64 t, %1; cvt.u32.u64 %0, t; }" : "=r"(a) : "l"(p));
    return a;
}
__device__ __forceinline__ void mma_f16(float (&c)[4], const uint32_t (&a)[4],
                                        const uint32_t (&b)[2]) {
    asm volatile(
        "mma.sync.aligned.m16n8k16.row.col.f32.f16.f16.f32 "
        "{%0,%1,%2,%3}, {%4,%5,%6,%7}, {%8,%9}, {%0,%1,%2,%3};"
        : "+f"(c[0]), "+f"(c[1]), "+f"(c[2]), "+f"(c[3])
        : "r"(a[0]), "r"(a[1]), "r"(a[2]), "r"(a[3]), "r"(b[0]), "r"(b[1]));
}
__device__ __forceinline__ void ldsm_x4(uint32_t (&r)[4], uint32_t a) {
    asm volatile("ldmatrix.sync.aligned.m8n8.x4.shared.b16 {%0,%1,%2,%3}, [%4];"
        : "=r"(r[0]), "=r"(r[1]), "=r"(r[2]), "=r"(r[3]) : "r"(a));
}
__device__ __forceinline__ void ldsm_x4t(uint32_t (&r)[4], uint32_t a) {
    asm volatile("ldmatrix.sync.aligned.m8n8.x4.trans.shared.b16 {%0,%1,%2,%3}, [%4];"
        : "=r"(r[0]), "=r"(r[1]), "=r"(r[2]), "=r"(r[3]) : "r"(a));
}
__device__ __forceinline__ void cpa16(uint32_t dst, const void* src) {
    asm volatile("cp.async.cg.shared.global [%0], [%1], 16;" :: "r"(dst), "l"(src) : "memory");
}
#define CP_COMMIT() asm volatile("cp.async.commit_group;" ::: "memory")

// ================= fp16 mma.sync GEMM, 128x128 tile, BK=64, 3-stage, ONE sync/chunk =================
// C[m0+i, n0+j] (+epilogue) = sum_k A(i,k) * B(j,k)
// TR==0: K-contiguous operand (slot S[row][k], 72-half stride, ldmatrix)
// TR==1: MN-contiguous operand (slot S[k][col], 136-half stride, ldmatrix.trans)
template <int TA, int TB, int EPI, int OUTH, int MULTI>
__global__ __launch_bounds__(256, 2)
void mm_tc(const __half* __restrict__ A, const __half* __restrict__ B,
           void* __restrict__ Cv, void* __restrict__ C1, void* __restrict__ C2,
           const __half* __restrict__ Vh, const __half* __restrict__ Hh,
           const float* __restrict__ Pf,
           int Kdim, int lda, int ldb, int ldc,
           size_t aG, size_t bG, size_t cG, int mZ) {
    extern __shared__ char smem[];
    const uint32_t sb = smem_to_u32(smem);

    const int tid = threadIdx.x;
    const int wid = tid >> 5, lane = tid & 31;
    const int wm = wid & 1, wn = wid >> 1;
    const int tr = lane >> 2, tq = lane & 3;

    const int graph = blockIdx.z;
    A += aG * graph;
    B += bG * graph;
    void* Cp;
    int n0c;
    if (MULTI) {
        void* bufs[3] = { Cv, C1, C2 };
        Cp = bufs[blockIdx.x >> 2];
        n0c = (blockIdx.x & 3) * BN;
    } else {
        Cp = OUTH ? (void*)((__half*)Cv + cG * graph)
                  : (void*)((float*)Cv + cG * graph);
        n0c = blockIdx.x * BN;
    }
    const int m0 = blockIdx.y * BM + mZ * graph;
    const int n0 = blockIdx.x * BN;

    // per-lane fragment base offsets (bytes within slot)
    uint32_t aBase, bBase;
    if (TA == 0) aBase = (uint32_t)((wm * 64 + (lane & 15)) * 144 + (lane >> 4) * 16);
    else         aBase = (uint32_t)(((lane >> 4) * 8 + (lane & 7)) * 272
                                    + (wm * 64 + ((lane >> 3) & 1) * 8) * 2);
    if (TB == 0) bBase = (uint32_t)((wn * 32 + (lane >> 4) * 8 + (lane & 7)) * 144
                                    + ((lane >> 3) & 1) * 16);
    else         bBase = (uint32_t)((((lane >> 3) & 1) * 8 + (lane & 7)) * 272
                                    + (wn * 32 + (lane >> 4) * 8) * 2);

    // cp.async one pipeline stage (BK=64)
    auto issue = [&](int stage, int ktile) {
        const int k0 = ktile * BK;
        uint32_t slotA = sb + (uint32_t)stage * STAGE_BYTES;
        uint32_t slotB = slotA + SLOT_BYTES;
        if (TA == 0) {
            int row = tid >> 1, hb = (tid & 1) * 32;     // halfs
            const __half* s = A + (size_t)(m0 + row) * lda + k0 + hb;
            uint32_t d = slotA + (uint32_t)(row * 144 + hb * 2);
#pragma unroll
            for (int j = 0; j < 4; ++j) cpa16(d + j * 16, s + j * 8);
        } else {
            int kr = tid >> 2, c = (tid & 3) * 32;
            const __half* s = A + (size_t)(k0 + kr) * lda + m0 + c;
            uint32_t d = slotA + (uint32_t)(kr * 272 + c * 2);
#pragma unroll
            for (int j = 0; j < 4; ++j) cpa16(d + j * 16, s + j * 8);
        }
        if (TB == 0) {
            int row = tid >> 1, hb = (tid & 1) * 32;
            const __half* s = B + (size_t)(n0 + row) * ldb + k0 + hb;
            uint32_t d = slotB + (uint32_t)(row * 144 + hb * 2);
#pragma unroll
            for (int j = 0; j < 4; ++j) cpa16(d + j * 16, s + j * 8);
        } else {
            int kr = tid >> 2, c = (tid & 3) * 32;
            const __half* s = B + (size_t)(k0 + kr) * ldb + n0 + c;
            uint32_t d = slotB + (uint32_t)(kr * 272 + c * 2);
#pragma unroll
            for (int j = 0; j < 4; ++j) cpa16(d + j * 16, s + j * 8);
        }
    };

    float acc[4][4][4] = {};

    issue(0, 0); CP_COMMIT();
    issue(1, 1); CP_COMMIT();

    const int nK = Kdim / BK;
    for (int kt = 0; kt < nK; ++kt) {
        if (nK - 1 - kt >= 1) {
            asm volatile("cp.async.wait_group 1;" ::: "memory");
        } else {
            asm volatile("cp.async.wait_group 0;" ::: "memory");
        }
        __syncthreads();    // single barrier: data visibility + slot-reuse protection

        uint32_t sA = sb + (uint32_t)(kt % NSTAGE) * STAGE_BYTES;
        uint32_t sB = sA + SLOT_BYTES;
#pragma unroll
        for (int ks = 0; ks < 4; ++ks) {          // four k16 steps per BK=64
            uint32_t afr[4][4], bfr[4][2];
            if (TA == 0) {
#pragma unroll
                for (int mi = 0; mi < 4; ++mi)
                    ldsm_x4(afr[mi], sA + aBase + (uint32_t)(mi * 2304 + ks * 32));
            } else {
#pragma unroll
                for (int mi = 0; mi < 4; ++mi)
                    ldsm_x4t(afr[mi], sA + aBase + (uint32_t)(mi * 32 + ks * 4352));
            }
            if (TB == 0) {
#pragma unroll
                for (int p = 0; p < 2; ++p) {
                    uint32_t t4[4];
                    ldsm_x4(t4, sB + bBase + (uint32_t)(p * 2304 + ks * 32));
                    bfr[2 * p + 0][0] = t4[0]; bfr[2 * p + 0][1] = t4[1];
                    bfr[2 * p + 1][0] = t4[2]; bfr[2 * p + 1][1] = t4[3];
                }
            } else {
#pragma unroll
                for (int p = 0; p < 2; ++p) {
                    uint32_t t4[4];
                    ldsm_x4t(t4, sB + bBase + (uint32_t)(p * 32 + ks * 4352));
                    bfr[2 * p + 0][0] = t4[0]; bfr[2 * p + 0][1] = t4[1];
                    bfr[2 * p + 1][0] = t4[2]; bfr[2 * p + 1][1] = t4[3];
                }
            }
#pragma unroll
            for (int mi = 0; mi < 4; ++mi)
#pragma unroll
                for (int ni = 0; ni < 4; ++ni)
                    mma_f16(acc[mi][ni], afr[mi], bfr[ni]);
        }
        // prefetch 2 chunks ahead AFTER compute: overwrites slot (kt-1)%3, which
        // every warp finished consuming before this iteration's __syncthreads.
        if (kt + 2 < nK) { issue((kt + 2) % NSTAGE, kt + 2); CP_COMMIT(); }
    }

    // ---------------- epilogue ----------------
#pragma unroll
    for (int mi = 0; mi < 4; ++mi) {
        int rbase = m0 + wm * 64 + mi * 16 + tr;
#pragma unroll
        for (int half = 0; half < 2; ++half) {
            size_t row = (size_t)rbase + half * 8;
            float dinv = 0.0f;
            if (EPI == EPI_ATT) dinv = 1.0f / Pf[row];
#pragma unroll
            for (int ni = 0; ni < 4; ++ni) {
                int col = n0c + wn * 32 + ni * 8 + tq * 2;
                float c0 = acc[mi][ni][half * 2 + 0];
                float c1 = acc[mi][ni][half * 2 + 1];
                float2 o;
                if (EPI == EPI_NONE) {
                    o.x = c0; o.y = c1;
                } else if (EPI == EPI_BIAS) {
                    float2 bv = *(const float2*)(Pf + col);
                    o.x = c0 + bv.x; o.y = c1 + bv.y;
                } else {
                    float2 vv = __half22float2(*(const __half2*)(Vh + row * HID + col));
                    float2 hh = __half22float2(*(const __half2*)(Hh + row * HID + col));
                    o.x = ((c0 + 4096.0f * vv.x) * dinv + hh.x) * 0.5f;
                    o.y = ((c1 + 4096.0f * vv.y) * dinv + hh.y) * 0.5f;
                }
                if (OUTH) {
                    *(__half2*)((__half*)Cp + row * (size_t)ldc + col) =
                        __floats2half2_rn(o.x, o.y);
                } else {
                    *(float2*)((float*)Cp + row * (size_t)ldc + col) = o;
                }
            }
        }
    }
}

// ================= elementwise kernels =================
__device__ __forceinline__ float wred(float v) {
#pragma unroll
    for (int o = 16; o; o >>= 1) v += __shfl_xor_sync(0xffffffffu, v, o);
    return v;
}

__global__ void cvt_half(const float4* __restrict__ in, __half2* __restrict__ out, int n4) {
    int i = blockIdx.x * blockDim.x + threadIdx.x;
    if (i < n4) {
        float4 v = in[i];
        out[2 * i + 0] = __floats2half2_rn(v.x, v.y);
        out[2 * i + 1] = __floats2half2_rn(v.z, v.w);
    }
}

// single launch converting all 7 weight tensors into the packed fp16 buffer
#define WSEG0 (HID * INCH / 4)      // fc0: 32768 float4
#define WSEGQ (HID * HID / 4)       // each qkv: 65536 float4
__global__ void cvt_weights(const float4* __restrict__ w0,
                            const float4* __restrict__ w1, const float4* __restrict__ w2,
                            const float4* __restrict__ w3, const float4* __restrict__ w4,
                            const float4* __restrict__ w5, const float4* __restrict__ w6,
                            __half2* __restrict__ out) {
    int i = blockIdx.x * blockDim.x + threadIdx.x;      // 0 .. WSEG0 + 6*WSEGQ
    const float4* src;
    int local;
    if (i < WSEG0) { src = w0; local = i; }
    else {
        int j = i - WSEG0;
        int seg = j / WSEGQ;
        local = j - seg * WSEGQ;
        const float4* ws[6] = { w1, w2, w3, w4, w5, w6 };
        src = ws[seg];
    }
    float4 v = src[local];
    out[2 * i + 0] = __floats2half2_rn(v.x, v.y);
    out[2 * i + 1] = __floats2half2_rn(v.z, v.w);
}

// LayerNorm + ReLU; IN16/OUT16 select fp16 input/output
template <int IN16, int OUT16>
__global__ void ln_relu(const void* __restrict__ inv, void* __restrict__ outv,
                        const float* __restrict__ g, const float* __restrict__ b) {
    size_t warp = ((size_t)blockIdx.x * blockDim.x + threadIdx.x) >> 5;
    int lane = threadIdx.x & 31;
    float4 v[4];
    float s = 0.0f, s2 = 0.0f;
#pragma unroll
    for (int c = 0; c < 4; ++c) {
        if (IN16) {
            const __half2* src = (const __half2*)((const __half*)inv + warp * HID);
            float2 a = __half22float2(src[(lane + 32 * c) * 2 + 0]);
            float2 d = __half22float2(src[(lane + 32 * c) * 2 + 1]);
            v[c].x = a.x; v[c].y = a.y; v[c].z = d.x; v[c].w = d.y;
        } else {
            v[c] = ((const float4*)((const float*)inv + warp * HID))[lane + 32 * c];
        }
        s  += v[c].x + v[c].y + v[c].z + v[c].w;
        s2 += v[c].x * v[c].x + v[c].y * v[c].y + v[c].z * v[c].z + v[c].w * v[c].w;
    }
    s = wred(s); s2 = wred(s2);
    float mu = s * (1.0f / HID);
    float var = s2 * (1.0f / HID) - mu * mu;
    float rstd = rsqrtf(var + LN_EPS);
#pragma unroll
    for (int c = 0; c < 4; ++c) {
        int i4 = lane + 32 * c;
        float4 gg = ((const float4*)g)[i4];
        float4 bb = ((const float4*)b)[i4];
        float4 o;
        o.x = fmaxf(0.0f, (v[c].x - mu) * rstd * gg.x + bb.x);
        o.y = fmaxf(0.0f, (v[c].y - mu) * rstd * gg.y + bb.y);
        o.z = fmaxf(0.0f, (v[c].z - mu) * rstd * gg.z + bb.z);
        o.w = fmaxf(0.0f, (v[c].w - mu) * rstd * gg.w + bb.w);
        if (OUT16) {
            __half2* dst = (__half2*)((__half*)outv + warp * HID);
            dst[i4 * 2 + 0] = __floats2half2_rn(o.x, o.y);
            dst[i4 * 2 + 1] = __floats2half2_rn(o.z, o.w);
        } else {
            ((float4*)((float*)outv + warp * HID))[i4] = o;
        }
    }
}

// k (fp16): eps-substitute, L2-normalize, store fp16; 8-row column partials (fp32).
__global__ void norm_k(__half* __restrict__ X, float* __restrict__ Part) {
    __shared__ float sacc[8][HID];
    int w = threadIdx.x >> 5, lane = threadIdx.x & 31;
    size_t row = (size_t)blockIdx.x * 8 + w;
    __half2* p = (__half2*)(X + row * HID);
    float2 f[8];
    float s2 = 0.0f;
#pragma unroll
    for (int c = 0; c < 8; ++c) {
        f[c] = __half22float2(p[lane + 32 * c]);
        if (f[c].x == 0.0f) f[c].x = QK_EPS;
        if (f[c].y == 0.0f) f[c].y = QK_EPS;
        s2 += f[c].x * f[c].x + f[c].y * f[c].y;
    }
    s2 = wred(s2);
    float rn = rsqrtf(s2);
#pragma unroll
    for (int c = 0; c < 8; ++c) {
        f[c].x *= rn; f[c].y *= rn;
        __half2 h2 = __floats2half2_rn(f[c].x, f[c].y);
        p[lane + 32 * c] = h2;
        float2 fq = __half22float2(h2);
        sacc[w][(lane + 32 * c) * 2 + 0] = fq.x;
        sacc[w][(lane + 32 * c) * 2 + 1] = fq.y;
    }
    __syncthreads();
#pragma unroll
    for (int ch = threadIdx.x; ch < HID; ch += 256) {
        float sum = 0.0f;
#pragma unroll
        for (int r = 0; r < 8; ++r) sum += sacc[r][ch];
        Part[(size_t)blockIdx.x * HID + ch] = sum;
    }
}

__global__ void ksum_reduce(const float* __restrict__ Part, float* __restrict__ KS) {
    int idx = blockIdx.x * blockDim.x + threadIdx.x;    // 16*512
    int graph = idx >> 9, ch = idx & 511;
    float s = 0.0f;
    const float* p = Part + ((size_t)graph * 512) * HID + ch;
#pragma unroll 8
    for (int b = 0; b < 512; ++b) s += p[(size_t)b * HID];
    KS[idx] = s;
}

// q (fp16): eps-substitute, normalize, store fp16; den[row] = dot(qn, ks) + N
__global__ void norm_q_den(__half* __restrict__ X, const float* __restrict__ KS,
                           float* __restrict__ den) {
    size_t warp = ((size_t)blockIdx.x * blockDim.x + threadIdx.x) >> 5;
    int lane = threadIdx.x & 31;
    int graph = (int)(warp >> 12);
    __half2* p = (__half2*)(X + warp * HID);
    const float2* kp = (const float2*)(KS + (size_t)graph * HID);
    float2 f[8];
    float s2 = 0.0f;
#pragma unroll
    for (int c = 0; c < 8; ++c) {
        f[c] = __half22float2(p[lane + 32 * c]);
        if (f[c].x == 0.0f) f[c].x = QK_EPS;
        if (f[c].y == 0.0f) f[c].y = QK_EPS;
        s2 += f[c].x * f[c].x + f[c].y * f[c].y;
    }
    s2 = wred(s2);
    float rn = rsqrtf(s2);
    float d = 0.0f;
#pragma unroll
    for (int c = 0; c < 8; ++c) {
        f[c].x *= rn; f[c].y *= rn;
        __half2 h2 = __floats2half2_rn(f[c].x, f[c].y);
        p[lane + 32 * c] = h2;
        float2 fq = __half22float2(h2);
        float2 kk = kp[lane + 32 * c];
        d += fq.x * kk.x + fq.y * kk.y;
    }
    d = wred(d);
    if (lane == 0) den[warp] = d + (float)NNODES;
}

// ================= launch =================
extern "C" void kernel_launch(void* const* d_in, const int* in_sizes, int n_in,
                              void* d_out, int out_size) {
    const float* x     = (const float*)d_in[0];
    const float* fc0_w = (const float*)d_in[1];
    const float* fc0_b = (const float*)d_in[2];
    const float* ln_g[3] = { (const float*)d_in[3], (const float*)d_in[8],  (const float*)d_in[13] };
    const float* ln_b[3] = { (const float*)d_in[4], (const float*)d_in[9],  (const float*)d_in[14] };
    const float* qw[2] = { (const float*)d_in[5],  (const float*)d_in[10] };
    const float* kw[2] = { (const float*)d_in[6],  (const float*)d_in[11] };
    const float* vw[2] = { (const float*)d_in[7],  (const float*)d_in[12] };
    float* out = (float*)d_out;
    // batch = repeat(arange(16), 4096): argsort and rev_perm are identities.

    __half *h, *q, *k, *v, *xh, *wh, *kvsh;
    float *t, *ksp, *ks, *den;
    cudaGetSymbolAddress((void**)&h,    g_h);
    cudaGetSymbolAddress((void**)&q,    g_q);
    cudaGetSymbolAddress((void**)&k,    g_k);
    cudaGetSymbolAddress((void**)&v,    g_v);
    cudaGetSymbolAddress((void**)&xh,   g_xh);
    cudaGetSymbolAddress((void**)&wh,   g_wh);
    cudaGetSymbolAddress((void**)&kvsh, g_kvsh);
    cudaGetSymbolAddress((void**)&t,    g_t);
    cudaGetSymbolAddress((void**)&ksp,  g_ksp);
    cudaGetSymbolAddress((void**)&ks,   g_ks);
    cudaGetSymbolAddress((void**)&den,  g_den);
    __half* th = (__half*)t;            // fp16 view for intermediate pre-LN tensors

    cudaFuncSetAttribute((const void*)mm_tc<0,0,EPI_BIAS,1,0>,
                         cudaFuncAttributeMaxDynamicSharedMemorySize, SMEM_BYTES);
    cudaFuncSetAttribute((const void*)mm_tc<0,0,EPI_NONE,1,1>,
                         cudaFuncAttributeMaxDynamicSharedMemorySize, SMEM_BYTES);
    cudaFuncSetAttribute((const void*)mm_tc<1,1,EPI_NONE,1,0>,
                         cudaFuncAttributeMaxDynamicSharedMemorySize, SMEM_BYTES);
    cudaFuncSetAttribute((const void*)mm_tc<0,1,EPI_ATT,1,0>,
                         cudaFuncAttributeMaxDynamicSharedMemorySize, SMEM_BYTES);
    cudaFuncSetAttribute((const void*)mm_tc<0,1,EPI_ATT,0,0>,
                         cudaFuncAttributeMaxDynamicSharedMemorySize, SMEM_BYTES);

    // fp16 weights: fc0 then per-layer [3*HID, HID] contiguous (q,k,v) — packed order
    __half* wh_fc0 = wh;
    __half* wh_l[2] = { wh + (size_t)HID * INCH,
                        wh + (size_t)HID * INCH + 3 * (size_t)HID * HID };

    cvt_half<<<(TOTAL * INCH / 4 + 255) / 256, 256>>>((const float4*)x, (__half2*)xh, TOTAL * INCH / 4);
    cvt_weights<<<(WSEG0 + 6 * WSEGQ + 255) / 256, 256>>>(
        (const float4*)fc0_w,
        (const float4*)qw[0], (const float4*)kw[0], (const float4*)vw[0],
        (const float4*)qw[1], (const float4*)kw[1], (const float4*)vw[1],
        (__half2*)wh);

    const int row_blocks = TOTAL / 8;

    // th = fp16(x @ fc0_w^T + b) ; h = fp16(relu(LN(th)))
    mm_tc<0,0,EPI_BIAS,1,0><<<dim3(HID / BN, TOTAL / BM), 256, SMEM_BYTES>>>(
        xh, wh_fc0, th, nullptr, nullptr, nullptr, nullptr, fc0_b,
        INCH, INCH, INCH, HID, 0, 0, 0, 0);
    ln_relu<1,1><<<row_blocks, 256>>>(th, h, ln_g[0], ln_b[0]);

    for (int l = 0; l < 2; ++l) {
        // merged QKV: B = [1536,512] fp16 weights; outputs q/k/v fp16
        mm_tc<0,0,EPI_NONE,1,1><<<dim3(12, TOTAL / BM), 256, SMEM_BYTES>>>(
            h, wh_l[l], q, k, v, nullptr, nullptr, nullptr,
            HID, HID, HID, HID, 0, 0, 0, 0);
        norm_k<<<KBLOCKS, 256>>>(k, ksp);
        ksum_reduce<<<(NGRAPH * HID) / 256, 256>>>(ksp, ks);
        norm_q_den<<<row_blocks, 256>>>(q, ks, den);
        // kvs[g][m,d] = sum_n k[g,n,m] * v[g,n,d]  — single wave (256 CTAs), fp16 out
        mm_tc<1,1,EPI_NONE,1,0><<<dim3(HID / BN, HID / BM, NGRAPH), 256, SMEM_BYTES>>>(
            k, v, kvsh, nullptr, nullptr, nullptr, nullptr, nullptr,
            NNODES, HID, HID, HID,
            (size_t)NNODES * HID, (size_t)NNODES * HID, (size_t)HID * HID, 0);
        // pre-LN attention output: layer0 -> fp16 th ; layer1 -> fp32 t (protect output)
        if (l == 0) {
            mm_tc<0,1,EPI_ATT,1,0><<<dim3(HID / BN, NNODES / BM, NGRAPH), 256, SMEM_BYTES>>>(
                q, kvsh, th, nullptr, nullptr, v, h, den,
                HID, HID, HID, HID, 0, (size_t)HID * HID, 0, NNODES);
            ln_relu<1,1><<<row_blocks, 256>>>(th, h, ln_g[1], ln_b[1]);
        } else {
            mm_tc<0,1,EPI_ATT,0,0><<<dim3(HID / BN, NNODES / BM, NGRAPH), 256, SMEM_BYTES>>>(
                q, kvsh, t, nullptr, nullptr, v, h, den,
                HID, HID, HID, HID, 0, (size_t)HID * HID, 0, NNODES);
            ln_relu<0,0><<<row_blocks, 256>>>(t, out, ln_g[2], ln_b[2]);
        }
    }
}

// round 13
// speedup vs baseline: 1.0449x; 1.0449x over previous
#include <cuda_runtime.h>
#include <cuda_fp16.h>
#include <cstdint>
#include <cstddef>

// ---------------- problem constants ----------------
#define TOTAL    65536          // B_GRAPHS * N_NODES
#define NGRAPH   16
#define NNODES   4096
#define INCH     256
#define HID      512
#define LN_EPS   1e-5f
#define QK_EPS   1e-6f
#define KBLOCKS  (TOTAL / 8)

// ---------------- GEMM tiling: 128x128 tile, warp 64x32, fp16, BK=32 ----------------
#define BM 128
#define BN 128
#define BK 32
// TR0 slot: 128 rows x 40 halfs (80 B/row) = 10240 B
// TR1 slot: 32 rows x 136 halfs (272 B/row) = 8704 B
#define SLOT_BYTES  10240
#define STAGE_BYTES (2 * SLOT_BYTES)
#define NSTAGE 5
#define SMEM_BYTES (NSTAGE * STAGE_BYTES)   // 102400 -> 2 CTAs/SM (200 KB)

// epilogue modes
#define EPI_NONE 0
#define EPI_BIAS 1
#define EPI_ATT  2

// ---------------- scratch (device globals; no allocation) ----------------
__device__ __half g_h  [(size_t)TOTAL * HID];
__device__ __half g_q  [(size_t)TOTAL * HID];
__device__ __half g_k  [(size_t)TOTAL * HID];
__device__ __half g_v  [(size_t)TOTAL * HID];
__device__ __half g_xh [(size_t)TOTAL * INCH];
__device__ __half g_wh [(size_t)(HID * INCH + 6 * HID * HID)];
__device__ __half g_kvsh[(size_t)NGRAPH * HID * HID];
__device__ float  g_t  [(size_t)TOTAL * HID];       // fp32 final layer; fp16 view for intermediates
__device__ float  g_ksp [(size_t)KBLOCKS * HID];
__device__ float  g_ks  [(size_t)NGRAPH * HID];
__device__ float  g_den [(size_t)TOTAL];

// ---------------- helpers ----------------
__device__ __forceinline__ uint32_t smem_to_u32(const void* p) {
    uint32_t a;
    asm("{ .reg .u64 t; cvta.to.shared.u64 t, %1; cvt.u32.u64 %0, t; }" : "=r"(a) : "l"(p));
    return a;
}
__device__ __forceinline__ void mma_f16(float (&c)[4], const uint32_t (&a)[4],
                                        const uint32_t (&b)[2]) {
    asm volatile(
        "mma.sync.aligned.m16n8k16.row.col.f32.f16.f16.f32 "
        "{%0,%1,%2,%3}, {%4,%5,%6,%7}, {%8,%9}, {%0,%1,%2,%3};"
        : "+f"(c[0]), "+f"(c[1]), "+f"(c[2]), "+f"(c[3])
        : "r"(a[0]), "r"(a[1]), "r"(a[2]), "r"(a[3]), "r"(b[0]), "r"(b[1]));
}
__device__ __forceinline__ void ldsm_x4(uint32_t (&r)[4], uint32_t a) {
    asm volatile("ldmatrix.sync.aligned.m8n8.x4.shared.b16 {%0,%1,%2,%3}, [%4];"
        : "=r"(r[0]), "=r"(r[1]), "=r"(r[2]), "=r"(r[3]) : "r"(a));
}
__device__ __forceinline__ void ldsm_x4t(uint32_t (&r)[4], uint32_t a) {
    asm volatile("ldmatrix.sync.aligned.m8n8.x4.trans.shared.b16 {%0,%1,%2,%3}, [%4];"
        : "=r"(r[0]), "=r"(r[1]), "=r"(r[2]), "=r"(r[3]) : "r"(a));
}
__device__ __forceinline__ void cpa16(uint32_t dst, const void* src) {
    asm volatile("cp.async.cg.shared.global [%0], [%1], 16;" :: "r"(dst), "l"(src) : "memory");
}
#define CP_COMMIT() asm volatile("cp.async.commit_group;" ::: "memory")

// ================= fp16 mma.sync GEMM, 128x128 tile, 5-stage, ONE sync/chunk =================
// C[m0+i, n0+j] (+epilogue) = sum_k A(i,k) * B(j,k)
// TR==0: K-contiguous operand (slot S[row][k], 40-half stride, ldmatrix)
// TR==1: MN-contiguous operand (slot S[k][col], 136-half stride, ldmatrix.trans)
template <int TA, int TB, int EPI, int OUTH, int MULTI>
__global__ __launch_bounds__(256, 2)
void mm_tc(const __half* __restrict__ A, const __half* __restrict__ B,
           void* __restrict__ Cv, void* __restrict__ C1, void* __restrict__ C2,
           const __half* __restrict__ Vh, const __half* __restrict__ Hh,
           const float* __restrict__ Pf,
           int Kdim, int lda, int ldb, int ldc,
           size_t aG, size_t bG, size_t cG, int mZ) {
    extern __shared__ char smem[];
    const uint32_t sb = smem_to_u32(smem);

    const int tid = threadIdx.x;
    const int wid = tid >> 5, lane = tid & 31;
    const int wm = wid & 1, wn = wid >> 1;
    const int tr = lane >> 2, tq = lane & 3;

    const int graph = blockIdx.z;
    A += aG * graph;
    B += bG * graph;
    void* Cp;
    int n0c;
    if (MULTI) {
        void* bufs[3] = { Cv, C1, C2 };
        Cp = bufs[blockIdx.x >> 2];
        n0c = (blockIdx.x & 3) * BN;
    } else {
        Cp = OUTH ? (void*)((__half*)Cv + cG * graph)
                  : (void*)((float*)Cv + cG * graph);
        n0c = blockIdx.x * BN;
    }
    const int m0 = blockIdx.y * BM + mZ * graph;
    const int n0 = blockIdx.x * BN;

    // per-lane fragment base offsets (bytes within slot)
    uint32_t aBase, bBase;
    if (TA == 0) aBase = (uint32_t)((wm * 64 + (lane & 15)) * 80 + (lane >> 4) * 16);
    else         aBase = (uint32_t)(((lane >> 4) * 8 + (lane & 7)) * 272
                                    + (wm * 64 + ((lane >> 3) & 1) * 8) * 2);
    if (TB == 0) bBase = (uint32_t)((wn * 32 + (lane >> 4) * 8 + (lane & 7)) * 80
                                    + ((lane >> 3) & 1) * 16);
    else         bBase = (uint32_t)((((lane >> 3) & 1) * 8 + (lane & 7)) * 272
                                    + (wn * 32 + (lane >> 4) * 8) * 2);

    // cp.async one pipeline stage
    auto issue = [&](int stage, int ktile) {
        const int k0 = ktile * BK;
        uint32_t slotA = sb + (uint32_t)stage * STAGE_BYTES;
        uint32_t slotB = slotA + SLOT_BYTES;
        if (TA == 0) {
            int row = tid >> 1, hb = (tid & 1) * 16;     // halfs
            const __half* s = A + (size_t)(m0 + row) * lda + k0 + hb;
            uint32_t d = slotA + (uint32_t)(row * 80 + hb * 2);
            cpa16(d, s); cpa16(d + 16, s + 8);
        } else {
            int kr = tid >> 3, c = (tid & 7) * 16;
            const __half* s = A + (size_t)(k0 + kr) * lda + m0 + c;
            uint32_t d = slotA + (uint32_t)(kr * 272 + c * 2);
            cpa16(d, s); cpa16(d + 16, s + 8);
        }
        if (TB == 0) {
            int row = tid >> 1, hb = (tid & 1) * 16;
            const __half* s = B + (size_t)(n0 + row) * ldb + k0 + hb;
            uint32_t d = slotB + (uint32_t)(row * 80 + hb * 2);
            cpa16(d, s); cpa16(d + 16, s + 8);
        } else {
            int kr = tid >> 3, c = (tid & 7) * 16;
            const __half* s = B + (size_t)(k0 + kr) * ldb + n0 + c;
            uint32_t d = slotB + (uint32_t)(kr * 272 + c * 2);
            cpa16(d, s); cpa16(d + 16, s + 8);
        }
    };

    float acc[4][4][4] = {};

    issue(0, 0); CP_COMMIT();
    issue(1, 1); CP_COMMIT();
    issue(2, 2); CP_COMMIT();
    issue(3, 3); CP_COMMIT();

    const int nK = Kdim / BK;
    for (int kt = 0; kt < nK; ++kt) {
        // wait for group kt: pending groups after it = min(3, nK-1-kt)
        int rem = nK - 1 - kt;
        if (rem >= 3) {
            asm volatile("cp.async.wait_group 3;" ::: "memory");
        } else if (rem == 2) {
            asm volatile("cp.async.wait_group 2;" ::: "memory");
        } else if (rem == 1) {
            asm volatile("cp.async.wait_group 1;" ::: "memory");
        } else {
            asm volatile("cp.async.wait_group 0;" ::: "memory");
        }
        __syncthreads();    // single barrier: data visibility + slot-reuse protection

        // prefetch 4 chunks ahead right after the barrier: overwrites slot
        // (kt+4)%5 = (kt-1)%5, consumed in iteration kt-1 and protected by
        // this iteration's __syncthreads. Loads overlap this chunk's MMAs.
        if (kt + 4 < nK) { issue((kt + 4) % NSTAGE, kt + 4); CP_COMMIT(); }

        uint32_t sA = sb + (uint32_t)(kt % NSTAGE) * STAGE_BYTES;
        uint32_t sB = sA + SLOT_BYTES;
#pragma unroll
        for (int ks = 0; ks < 2; ++ks) {          // two k16 steps per BK=32
            uint32_t afr[4][4], bfr[4][2];
            if (TA == 0) {
#pragma unroll
                for (int mi = 0; mi < 4; ++mi)
                    ldsm_x4(afr[mi], sA + aBase + (uint32_t)(mi * 1280 + ks * 32));
            } else {
#pragma unroll
                for (int mi = 0; mi < 4; ++mi)
                    ldsm_x4t(afr[mi], sA + aBase + (uint32_t)(mi * 32 + ks * 4352));
            }
            if (TB == 0) {
#pragma unroll
                for (int p = 0; p < 2; ++p) {
                    uint32_t t4[4];
                    ldsm_x4(t4, sB + bBase + (uint32_t)(p * 1280 + ks * 32));
                    bfr[2 * p + 0][0] = t4[0]; bfr[2 * p + 0][1] = t4[1];
                    bfr[2 * p + 1][0] = t4[2]; bfr[2 * p + 1][1] = t4[3];
                }
            } else {
#pragma unroll
                for (int p = 0; p < 2; ++p) {
                    uint32_t t4[4];
                    ldsm_x4t(t4, sB + bBase + (uint32_t)(p * 32 + ks * 4352));
                    bfr[2 * p + 0][0] = t4[0]; bfr[2 * p + 0][1] = t4[1];
                    bfr[2 * p + 1][0] = t4[2]; bfr[2 * p + 1][1] = t4[3];
                }
            }
#pragma unroll
            for (int mi = 0; mi < 4; ++mi)
#pragma unroll
                for (int ni = 0; ni < 4; ++ni)
                    mma_f16(acc[mi][ni], afr[mi], bfr[ni]);
        }
    }

    // ---------------- epilogue ----------------
#pragma unroll
    for (int mi = 0; mi < 4; ++mi) {
        int rbase = m0 + wm * 64 + mi * 16 + tr;
#pragma unroll
        for (int half = 0; half < 2; ++half) {
            size_t row = (size_t)rbase + half * 8;
            float dinv = 0.0f;
            if (EPI == EPI_ATT) dinv = 1.0f / Pf[row];
#pragma unroll
            for (int ni = 0; ni < 4; ++ni) {
                int col = n0c + wn * 32 + ni * 8 + tq * 2;
                float c0 = acc[mi][ni][half * 2 + 0];
                float c1 = acc[mi][ni][half * 2 + 1];
                float2 o;
                if (EPI == EPI_NONE) {
                    o.x = c0; o.y = c1;
                } else if (EPI == EPI_BIAS) {
                    float2 bv = *(const float2*)(Pf + col);
                    o.x = c0 + bv.x; o.y = c1 + bv.y;
                } else {
                    float2 vv = __half22float2(*(const __half2*)(Vh + row * HID + col));
                    float2 hh = __half22float2(*(const __half2*)(Hh + row * HID + col));
                    o.x = ((c0 + 4096.0f * vv.x) * dinv + hh.x) * 0.5f;
                    o.y = ((c1 + 4096.0f * vv.y) * dinv + hh.y) * 0.5f;
                }
                if (OUTH) {
                    *(__half2*)((__half*)Cp + row * (size_t)ldc + col) =
                        __floats2half2_rn(o.x, o.y);
                } else {
                    *(float2*)((float*)Cp + row * (size_t)ldc + col) = o;
                }
            }
        }
    }
}

// ================= elementwise kernels =================
__device__ __forceinline__ float wred(float v) {
#pragma unroll
    for (int o = 16; o; o >>= 1) v += __shfl_xor_sync(0xffffffffu, v, o);
    return v;
}

__global__ void cvt_half(const float4* __restrict__ in, __half2* __restrict__ out, int n4) {
    int i = blockIdx.x * blockDim.x + threadIdx.x;
    if (i < n4) {
        float4 v = in[i];
        out[2 * i + 0] = __floats2half2_rn(v.x, v.y);
        out[2 * i + 1] = __floats2half2_rn(v.z, v.w);
    }
}

// single launch converting all 7 weight tensors into the packed fp16 buffer
#define WSEG0 (HID * INCH / 4)      // fc0: 32768 float4
#define WSEGQ (HID * HID / 4)       // each qkv: 65536 float4
__global__ void cvt_weights(const float4* __restrict__ w0,
                            const float4* __restrict__ w1, const float4* __restrict__ w2,
                            const float4* __restrict__ w3, const float4* __restrict__ w4,
                            const float4* __restrict__ w5, const float4* __restrict__ w6,
                            __half2* __restrict__ out) {
    int i = blockIdx.x * blockDim.x + threadIdx.x;      // 0 .. WSEG0 + 6*WSEGQ
    const float4* src;
    int local;
    if (i < WSEG0) { src = w0; local = i; }
    else {
        int j = i - WSEG0;
        int seg = j / WSEGQ;
        local = j - seg * WSEGQ;
        const float4* ws[6] = { w1, w2, w3, w4, w5, w6 };
        src = ws[seg];
    }
    float4 v = src[local];
    out[2 * i + 0] = __floats2half2_rn(v.x, v.y);
    out[2 * i + 1] = __floats2half2_rn(v.z, v.w);
}

// LayerNorm + ReLU; IN16/OUT16 select fp16 input/output
template <int IN16, int OUT16>
__global__ void ln_relu(const void* __restrict__ inv, void* __restrict__ outv,
                        const float* __restrict__ g, const float* __restrict__ b) {
    size_t warp = ((size_t)blockIdx.x * blockDim.x + threadIdx.x) >> 5;
    int lane = threadIdx.x & 31;
    float4 v[4];
    float s = 0.0f, s2 = 0.0f;
#pragma unroll
    for (int c = 0; c < 4; ++c) {
        if (IN16) {
            const __half2* src = (const __half2*)((const __half*)inv + warp * HID);
            float2 a = __half22float2(src[(lane + 32 * c) * 2 + 0]);
            float2 d = __half22float2(src[(lane + 32 * c) * 2 + 1]);
            v[c].x = a.x; v[c].y = a.y; v[c].z = d.x; v[c].w = d.y;
        } else {
            v[c] = ((const float4*)((const float*)inv + warp * HID))[lane + 32 * c];
        }
        s  += v[c].x + v[c].y + v[c].z + v[c].w;
        s2 += v[c].x * v[c].x + v[c].y * v[c].y + v[c].z * v[c].z + v[c].w * v[c].w;
    }
    s = wred(s); s2 = wred(s2);
    float mu = s * (1.0f / HID);
    float var = s2 * (1.0f / HID) - mu * mu;
    float rstd = rsqrtf(var + LN_EPS);
#pragma unroll
    for (int c = 0; c < 4; ++c) {
        int i4 = lane + 32 * c;
        float4 gg = ((const float4*)g)[i4];
        float4 bb = ((const float4*)b)[i4];
        float4 o;
        o.x = fmaxf(0.0f, (v[c].x - mu) * rstd * gg.x + bb.x);
        o.y = fmaxf(0.0f, (v[c].y - mu) * rstd * gg.y + bb.y);
        o.z = fmaxf(0.0f, (v[c].z - mu) * rstd * gg.z + bb.z);
        o.w = fmaxf(0.0f, (v[c].w - mu) * rstd * gg.w + bb.w);
        if (OUT16) {
            __half2* dst = (__half2*)((__half*)outv + warp * HID);
            dst[i4 * 2 + 0] = __floats2half2_rn(o.x, o.y);
            dst[i4 * 2 + 1] = __floats2half2_rn(o.z, o.w);
        } else {
            ((float4*)((float*)outv + warp * HID))[i4] = o;
        }
    }
}

// k (fp16): eps-substitute, L2-normalize, store fp16; 8-row column partials (fp32).
__global__ void norm_k(__half* __restrict__ X, float* __restrict__ Part) {
    __shared__ float sacc[8][HID];
    int w = threadIdx.x >> 5, lane = threadIdx.x & 31;
    size_t row = (size_t)blockIdx.x * 8 + w;
    __half2* p = (__half2*)(X + row * HID);
    float2 f[8];
    float s2 = 0.0f;
#pragma unroll
    for (int c = 0; c < 8; ++c) {
        f[c] = __half22float2(p[lane + 32 * c]);
        if (f[c].x == 0.0f) f[c].x = QK_EPS;
        if (f[c].y == 0.0f) f[c].y = QK_EPS;
        s2 += f[c].x * f[c].x + f[c].y * f[c].y;
    }
    s2 = wred(s2);
    float rn = rsqrtf(s2);
#pragma unroll
    for (int c = 0; c < 8; ++c) {
        f[c].x *= rn; f[c].y *= rn;
        __half2 h2 = __floats2half2_rn(f[c].x, f[c].y);
        p[lane + 32 * c] = h2;
        float2 fq = __half22float2(h2);
        sacc[w][(lane + 32 * c) * 2 + 0] = fq.x;
        sacc[w][(lane + 32 * c) * 2 + 1] = fq.y;
    }
    __syncthreads();
#pragma unroll
    for (int ch = threadIdx.x; ch < HID; ch += 256) {
        float sum = 0.0f;
#pragma unroll
        for (int r = 0; r < 8; ++r) sum += sacc[r][ch];
        Part[(size_t)blockIdx.x * HID + ch] = sum;
    }
}

__global__ void ksum_reduce(const float* __restrict__ Part, float* __restrict__ KS) {
    int idx = blockIdx.x * blockDim.x + threadIdx.x;    // 16*512
    int graph = idx >> 9, ch = idx & 511;
    float s = 0.0f;
    const float* p = Part + ((size_t)graph * 512) * HID + ch;
#pragma unroll 8
    for (int b = 0; b < 512; ++b) s += p[(size_t)b * HID];
    KS[idx] = s;
}

// q (fp16): eps-substitute, normalize, store fp16; den[row] = dot(qn, ks) + N
__global__ void norm_q_den(__half* __restrict__ X, const float* __restrict__ KS,
                           float* __restrict__ den) {
    size_t warp = ((size_t)blockIdx.x * blockDim.x + threadIdx.x) >> 5;
    int lane = threadIdx.x & 31;
    int graph = (int)(warp >> 12);
    __half2* p = (__half2*)(X + warp * HID);
    const float2* kp = (const float2*)(KS + (size_t)graph * HID);
    float2 f[8];
    float s2 = 0.0f;
#pragma unroll
    for (int c = 0; c < 8; ++c) {
        f[c] = __half22float2(p[lane + 32 * c]);
        if (f[c].x == 0.0f) f[c].x = QK_EPS;
        if (f[c].y == 0.0f) f[c].y = QK_EPS;
        s2 += f[c].x * f[c].x + f[c].y * f[c].y;
    }
    s2 = wred(s2);
    float rn = rsqrtf(s2);
    float d = 0.0f;
#pragma unroll
    for (int c = 0; c < 8; ++c) {
        f[c].x *= rn; f[c].y *= rn;
        __half2 h2 = __floats2half2_rn(f[c].x, f[c].y);
        p[lane + 32 * c] = h2;
        float2 fq = __half22float2(h2);
        float2 kk = kp[lane + 32 * c];
        d += fq.x * kk.x + fq.y * kk.y;
    }
    d = wred(d);
    if (lane == 0) den[warp] = d + (float)NNODES;
}

// ================= launch =================
extern "C" void kernel_launch(void* const* d_in, const int* in_sizes, int n_in,
                              void* d_out, int out_size) {
    const float* x     = (const float*)d_in[0];
    const float* fc0_w = (const float*)d_in[1];
    const float* fc0_b = (const float*)d_in[2];
    const float* ln_g[3] = { (const float*)d_in[3], (const float*)d_in[8],  (const float*)d_in[13] };
    const float* ln_b[3] = { (const float*)d_in[4], (const float*)d_in[9],  (const float*)d_in[14] };
    const float* qw[2] = { (const float*)d_in[5],  (const float*)d_in[10] };
    const float* kw[2] = { (const float*)d_in[6],  (const float*)d_in[11] };
    const float* vw[2] = { (const float*)d_in[7],  (const float*)d_in[12] };
    float* out = (float*)d_out;
    // batch = repeat(arange(16), 4096): argsort and rev_perm are identities.

    __half *h, *q, *k, *v, *xh, *wh, *kvsh;
    float *t, *ksp, *ks, *den;
    cudaGetSymbolAddress((void**)&h,    g_h);
    cudaGetSymbolAddress((void**)&q,    g_q);
    cudaGetSymbolAddress((void**)&k,    g_k);
    cudaGetSymbolAddress((void**)&v,    g_v);
    cudaGetSymbolAddress((void**)&xh,   g_xh);
    cudaGetSymbolAddress((void**)&wh,   g_wh);
    cudaGetSymbolAddress((void**)&kvsh, g_kvsh);
    cudaGetSymbolAddress((void**)&t,    g_t);
    cudaGetSymbolAddress((void**)&ksp,  g_ksp);
    cudaGetSymbolAddress((void**)&ks,   g_ks);
    cudaGetSymbolAddress((void**)&den,  g_den);
    __half* th = (__half*)t;            // fp16 view for intermediate pre-LN tensors

    cudaFuncSetAttribute((const void*)mm_tc<0,0,EPI_BIAS,1,0>,
                         cudaFuncAttributeMaxDynamicSharedMemorySize, SMEM_BYTES);
    cudaFuncSetAttribute((const void*)mm_tc<0,0,EPI_NONE,1,1>,
                         cudaFuncAttributeMaxDynamicSharedMemorySize, SMEM_BYTES);
    cudaFuncSetAttribute((const void*)mm_tc<1,1,EPI_NONE,1,0>,
                         cudaFuncAttributeMaxDynamicSharedMemorySize, SMEM_BYTES);
    cudaFuncSetAttribute((const void*)mm_tc<0,1,EPI_ATT,1,0>,
                         cudaFuncAttributeMaxDynamicSharedMemorySize, SMEM_BYTES);
    cudaFuncSetAttribute((const void*)mm_tc<0,1,EPI_ATT,0,0>,
                         cudaFuncAttributeMaxDynamicSharedMemorySize, SMEM_BYTES);

    // fp16 weights: fc0 then per-layer [3*HID, HID] contiguous (q,k,v) — packed order
    __half* wh_fc0 = wh;
    __half* wh_l[2] = { wh + (size_t)HID * INCH,
                        wh + (size_t)HID * INCH + 3 * (size_t)HID * HID };

    cvt_half<<<(TOTAL * INCH / 4 + 255) / 256, 256>>>((const float4*)x, (__half2*)xh, TOTAL * INCH / 4);
    cvt_weights<<<(WSEG0 + 6 * WSEGQ + 255) / 256, 256>>>(
        (const float4*)fc0_w,
        (const float4*)qw[0], (const float4*)kw[0], (const float4*)vw[0],
        (const float4*)qw[1], (const float4*)kw[1], (const float4*)vw[1],
        (__half2*)wh);

    const int row_blocks = TOTAL / 8;

    // th = fp16(x @ fc0_w^T + b) ; h = fp16(relu(LN(th)))
    mm_tc<0,0,EPI_BIAS,1,0><<<dim3(HID / BN, TOTAL / BM), 256, SMEM_BYTES>>>(
        xh, wh_fc0, th, nullptr, nullptr, nullptr, nullptr, fc0_b,
        INCH, INCH, INCH, HID, 0, 0, 0, 0);
    ln_relu<1,1><<<row_blocks, 256>>>(th, h, ln_g[0], ln_b[0]);

    for (int l = 0; l < 2; ++l) {
        // merged QKV: B = [1536,512] fp16 weights; outputs q/k/v fp16
        mm_tc<0,0,EPI_NONE,1,1><<<dim3(12, TOTAL / BM), 256, SMEM_BYTES>>>(
            h, wh_l[l], q, k, v, nullptr, nullptr, nullptr,
            HID, HID, HID, HID, 0, 0, 0, 0);
        norm_k<<<KBLOCKS, 256>>>(k, ksp);
        ksum_reduce<<<(NGRAPH * HID) / 256, 256>>>(ksp, ks);
        norm_q_den<<<row_blocks, 256>>>(q, ks, den);
        // kvs[g][m,d] = sum_n k[g,n,m] * v[g,n,d]  — single wave (256 CTAs), fp16 out
        mm_tc<1,1,EPI_NONE,1,0><<<dim3(HID / BN, HID / BM, NGRAPH), 256, SMEM_BYTES>>>(
            k, v, kvsh, nullptr, nullptr, nullptr, nullptr, nullptr,
            NNODES, HID, HID, HID,
            (size_t)NNODES * HID, (size_t)NNODES * HID, (size_t)HID * HID, 0);
        // pre-LN attention output: layer0 -> fp16 th ; layer1 -> fp32 t (protect output)
        if (l == 0) {
            mm_tc<0,1,EPI_ATT,1,0><<<dim3(HID / BN, NNODES / BM, NGRAPH), 256, SMEM_BYTES>>>(
                q, kvsh, th, nullptr, nullptr, v, h, den,
                HID, HID, HID, HID, 0, (size_t)HID * HID, 0, NNODES);
            ln_relu<1,1><<<row_blocks, 256>>>(th, h, ln_g[1], ln_b[1]);
        } else {
            mm_tc<0,1,EPI_ATT,0,0><<<dim3(HID / BN, NNODES / BM, NGRAPH), 256, SMEM_BYTES>>>(
                q, kvsh, t, nullptr, nullptr, v, h, den,
                HID, HID, HID, HID, 0, (size_t)HID * HID, 0, NNODES);
            ln_relu<0,0><<<row_blocks, 256>>>(t, out, ln_g[2], ln_b[2]);
        }
    }
}

// round 14
// speedup vs baseline: 1.1100x; 1.0624x over previous
#include <cuda_runtime.h>
#include <cuda_fp16.h>
#include <cstdint>
#include <cstddef>

// ---------------- problem constants ----------------
#define TOTAL    65536          // B_GRAPHS * N_NODES
#define NGRAPH   16
#define NNODES   4096
#define INCH     256
#define HID      512
#define LN_EPS   1e-5f
#define QK_EPS   1e-6f
#define KBLOCKS  (TOTAL / 8)

// ---------------- GEMM tiling: 128x128 tile, warp 64x32, fp16, BK=32 ----------------
#define BM 128
#define BN 128
#define BK 32
// TR0 slot: 128 rows x 40 halfs (80 B/row) = 10240 B
// TR1 slot: 32 rows x 136 halfs (272 B/row) = 8704 B
#define SLOT_BYTES  10240
#define STAGE_BYTES (2 * SLOT_BYTES)
#define NSTAGE 4
#define SMEM_BYTES (NSTAGE * STAGE_BYTES)   // 81920 -> 2 CTAs/SM (160 KB)

// epilogue modes
#define EPI_NONE 0
#define EPI_BIAS 1
#define EPI_ATT  2

// ---------------- scratch (device globals; no allocation) ----------------
__device__ __half g_h  [(size_t)TOTAL * HID];
__device__ __half g_q  [(size_t)TOTAL * HID];
__device__ __half g_k  [(size_t)TOTAL * HID];
__device__ __half g_v  [(size_t)TOTAL * HID];
__device__ __half g_xh [(size_t)TOTAL * INCH];
__device__ __half g_wh [(size_t)(HID * INCH + 6 * HID * HID)];
__device__ __half g_kvsh[(size_t)NGRAPH * HID * HID];
__device__ float  g_t  [(size_t)TOTAL * HID];       // fp32 final layer; fp16 view for intermediates
__device__ float  g_ksp [(size_t)KBLOCKS * HID];
__device__ float  g_ks  [(size_t)NGRAPH * HID];
__device__ float  g_den [(size_t)TOTAL];

// ---------------- helpers ----------------
__device__ __forceinline__ uint32_t smem_to_u32(const void* p) {
    uint32_t a;
    asm("{ .reg .u64 t; cvta.to.shared.u64 t, %1; cvt.u32.u64 %0, t; }" : "=r"(a) : "l"(p));
    return a;
}
__device__ __forceinline__ void mma_f16(float (&c)[4], const uint32_t (&a)[4],
                                        const uint32_t (&b)[2]) {
    asm volatile(
        "mma.sync.aligned.m16n8k16.row.col.f32.f16.f16.f32 "
        "{%0,%1,%2,%3}, {%4,%5,%6,%7}, {%8,%9}, {%0,%1,%2,%3};"
        : "+f"(c[0]), "+f"(c[1]), "+f"(c[2]), "+f"(c[3])
        : "r"(a[0]), "r"(a[1]), "r"(a[2]), "r"(a[3]), "r"(b[0]), "r"(b[1]));
}
__device__ __forceinline__ void ldsm_x4(uint32_t (&r)[4], uint32_t a) {
    asm volatile("ldmatrix.sync.aligned.m8n8.x4.shared.b16 {%0,%1,%2,%3}, [%4];"
        : "=r"(r[0]), "=r"(r[1]), "=r"(r[2]), "=r"(r[3]) : "r"(a));
}
__device__ __forceinline__ void ldsm_x4t(uint32_t (&r)[4], uint32_t a) {
    asm volatile("ldmatrix.sync.aligned.m8n8.x4.trans.shared.b16 {%0,%1,%2,%3}, [%4];"
        : "=r"(r[0]), "=r"(r[1]), "=r"(r[2]), "=r"(r[3]) : "r"(a));
}
__device__ __forceinline__ void cpa16(uint32_t dst, const void* src) {
    asm volatile("cp.async.cg.shared.global [%0], [%1], 16;" :: "r"(dst), "l"(src) : "memory");
}
#define CP_COMMIT() asm volatile("cp.async.commit_group;" ::: "memory")

// ================= fp16 mma.sync GEMM, 128x128 tile, 4-stage, ONE sync/chunk =================
// C[m0+i, n0+j] (+epilogue) = sum_k A(i,k) * B(j,k)
// TR==0: K-contiguous operand (slot S[row][k], 40-half stride, ldmatrix)
// TR==1: MN-contiguous operand (slot S[k][col], 136-half stride, ldmatrix.trans)
template <int TA, int TB, int EPI, int OUTH, int MULTI>
__global__ __launch_bounds__(256, 2)
void mm_tc(const __half* __restrict__ A, const __half* __restrict__ B,
           void* __restrict__ Cv, void* __restrict__ C1, void* __restrict__ C2,
           const __half* __restrict__ Vh, const __half* __restrict__ Hh,
           const float* __restrict__ Pf,
           int Kdim, int lda, int ldb, int ldc,
           size_t aG, size_t bG, size_t cG, int mZ) {
    extern __shared__ char smem[];
    const uint32_t sb = smem_to_u32(smem);

    const int tid = threadIdx.x;
    const int wid = tid >> 5, lane = tid & 31;
    const int wm = wid & 1, wn = wid >> 1;
    const int tr = lane >> 2, tq = lane & 3;

    const int graph = blockIdx.z;
    A += aG * graph;
    B += bG * graph;
    void* Cp;
    int n0c;
    if (MULTI) {
        void* bufs[3] = { Cv, C1, C2 };
        Cp = bufs[blockIdx.x >> 2];
        n0c = (blockIdx.x & 3) * BN;
    } else {
        Cp = OUTH ? (void*)((__half*)Cv + cG * graph)
                  : (void*)((float*)Cv + cG * graph);
        n0c = blockIdx.x * BN;
    }
    const int m0 = blockIdx.y * BM + mZ * graph;
    const int n0 = blockIdx.x * BN;

    // per-lane fragment base offsets (bytes within slot)
    uint32_t aBase, bBase;
    if (TA == 0) aBase = (uint32_t)((wm * 64 + (lane & 15)) * 80 + (lane >> 4) * 16);
    else         aBase = (uint32_t)(((lane >> 4) * 8 + (lane & 7)) * 272
                                    + (wm * 64 + ((lane >> 3) & 1) * 8) * 2);
    if (TB == 0) bBase = (uint32_t)((wn * 32 + (lane >> 4) * 8 + (lane & 7)) * 80
                                    + ((lane >> 3) & 1) * 16);
    else         bBase = (uint32_t)((((lane >> 3) & 1) * 8 + (lane & 7)) * 272
                                    + (wn * 32 + (lane >> 4) * 8) * 2);

    // cp.async one pipeline stage
    auto issue = [&](int stage, int ktile) {
        const int k0 = ktile * BK;
        uint32_t slotA = sb + (uint32_t)stage * STAGE_BYTES;
        uint32_t slotB = slotA + SLOT_BYTES;
        if (TA == 0) {
            int row = tid >> 1, hb = (tid & 1) * 16;     // halfs
            const __half* s = A + (size_t)(m0 + row) * lda + k0 + hb;
            uint32_t d = slotA + (uint32_t)(row * 80 + hb * 2);
            cpa16(d, s); cpa16(d + 16, s + 8);
        } else {
            int kr = tid >> 3, c = (tid & 7) * 16;
            const __half* s = A + (size_t)(k0 + kr) * lda + m0 + c;
            uint32_t d = slotA + (uint32_t)(kr * 272 + c * 2);
            cpa16(d, s); cpa16(d + 16, s + 8);
        }
        if (TB == 0) {
            int row = tid >> 1, hb = (tid & 1) * 16;
            const __half* s = B + (size_t)(n0 + row) * ldb + k0 + hb;
            uint32_t d = slotB + (uint32_t)(row * 80 + hb * 2);
            cpa16(d, s); cpa16(d + 16, s + 8);
        } else {
            int kr = tid >> 3, c = (tid & 7) * 16;
            const __half* s = B + (size_t)(k0 + kr) * ldb + n0 + c;
            uint32_t d = slotB + (uint32_t)(kr * 272 + c * 2);
            cpa16(d, s); cpa16(d + 16, s + 8);
        }
    };

    float acc[4][4][4] = {};

    issue(0, 0); CP_COMMIT();
    issue(1, 1); CP_COMMIT();
    issue(2, 2); CP_COMMIT();

    const int nK = Kdim / BK;
    for (int kt = 0; kt < nK; ++kt) {
        int rem = nK - 1 - kt;
        if (rem >= 2) {
            asm volatile("cp.async.wait_group 2;" ::: "memory");
        } else if (rem == 1) {
            asm volatile("cp.async.wait_group 1;" ::: "memory");
        } else {
            asm volatile("cp.async.wait_group 0;" ::: "memory");
        }
        __syncthreads();    // single barrier: data visibility + slot-reuse protection

        uint32_t sA = sb + (uint32_t)(kt % NSTAGE) * STAGE_BYTES;
        uint32_t sB = sA + SLOT_BYTES;
#pragma unroll
        for (int ks = 0; ks < 2; ++ks) {          // two k16 steps per BK=32
            uint32_t afr[4][4], bfr[4][2];
            if (TA == 0) {
#pragma unroll
                for (int mi = 0; mi < 4; ++mi)
                    ldsm_x4(afr[mi], sA + aBase + (uint32_t)(mi * 1280 + ks * 32));
            } else {
#pragma unroll
                for (int mi = 0; mi < 4; ++mi)
                    ldsm_x4t(afr[mi], sA + aBase + (uint32_t)(mi * 32 + ks * 4352));
            }
            if (TB == 0) {
#pragma unroll
                for (int p = 0; p < 2; ++p) {
                    uint32_t t4[4];
                    ldsm_x4(t4, sB + bBase + (uint32_t)(p * 1280 + ks * 32));
                    bfr[2 * p + 0][0] = t4[0]; bfr[2 * p + 0][1] = t4[1];
                    bfr[2 * p + 1][0] = t4[2]; bfr[2 * p + 1][1] = t4[3];
                }
            } else {
#pragma unroll
                for (int p = 0; p < 2; ++p) {
                    uint32_t t4[4];
                    ldsm_x4t(t4, sB + bBase + (uint32_t)(p * 32 + ks * 4352));
                    bfr[2 * p + 0][0] = t4[0]; bfr[2 * p + 0][1] = t4[1];
                    bfr[2 * p + 1][0] = t4[2]; bfr[2 * p + 1][1] = t4[3];
                }
            }
#pragma unroll
            for (int mi = 0; mi < 4; ++mi)
#pragma unroll
                for (int ni = 0; ni < 4; ++ni)
                    mma_f16(acc[mi][ni], afr[mi], bfr[ni]);
        }
        // prefetch 3 chunks ahead AFTER compute: overwrites slot (kt-1)%4, which
        // every warp finished consuming before this iteration's __syncthreads.
        if (kt + 3 < nK) { issue((kt + 3) % NSTAGE, kt + 3); CP_COMMIT(); }
    }

    // ---------------- epilogue ----------------
#pragma unroll
    for (int mi = 0; mi < 4; ++mi) {
        int rbase = m0 + wm * 64 + mi * 16 + tr;
#pragma unroll
        for (int half = 0; half < 2; ++half) {
            size_t row = (size_t)rbase + half * 8;
            float dinv = 0.0f;
            if (EPI == EPI_ATT) dinv = 1.0f / Pf[row];
#pragma unroll
            for (int ni = 0; ni < 4; ++ni) {
                int col = n0c + wn * 32 + ni * 8 + tq * 2;
                float c0 = acc[mi][ni][half * 2 + 0];
                float c1 = acc[mi][ni][half * 2 + 1];
                float2 o;
                if (EPI == EPI_NONE) {
                    o.x = c0; o.y = c1;
                } else if (EPI == EPI_BIAS) {
                    float2 bv = *(const float2*)(Pf + col);
                    o.x = c0 + bv.x; o.y = c1 + bv.y;
                } else {
                    float2 vv = __half22float2(*(const __half2*)(Vh + row * HID + col));
                    float2 hh = __half22float2(*(const __half2*)(Hh + row * HID + col));
                    o.x = ((c0 + 4096.0f * vv.x) * dinv + hh.x) * 0.5f;
                    o.y = ((c1 + 4096.0f * vv.y) * dinv + hh.y) * 0.5f;
                }
                if (OUTH) {
                    *(__half2*)((__half*)Cp + row * (size_t)ldc + col) =
                        __floats2half2_rn(o.x, o.y);
                } else {
                    *(float2*)((float*)Cp + row * (size_t)ldc + col) = o;
                }
            }
        }
    }
}

// ================= elementwise kernels =================
__device__ __forceinline__ float wred(float v) {
#pragma unroll
    for (int o = 16; o; o >>= 1) v += __shfl_xor_sync(0xffffffffu, v, o);
    return v;
}

// single launch converting x AND all 7 weight tensors into fp16 buffers
#define XSEG  (TOTAL * INCH / 4)    // x: 4194304 float4
#define WSEG0 (HID * INCH / 4)      // fc0: 32768 float4
#define WSEGQ (HID * HID / 4)       // each qkv: 65536 float4
#define CVT_TOTAL (XSEG + WSEG0 + 6 * WSEGQ)
__global__ void cvt_all(const float4* __restrict__ xin,
                        const float4* __restrict__ w0,
                        const float4* __restrict__ w1, const float4* __restrict__ w2,
                        const float4* __restrict__ w3, const float4* __restrict__ w4,
                        const float4* __restrict__ w5, const float4* __restrict__ w6,
                        __half2* __restrict__ xh_out, __half2* __restrict__ wh_out) {
    int i = blockIdx.x * blockDim.x + threadIdx.x;
    if (i >= CVT_TOTAL) return;
    const float4* src;
    __half2* dst;
    int local;
    if (i < XSEG) {
        src = xin; dst = xh_out; local = i;
    } else {
        int j = i - XSEG;
        dst = wh_out;
        if (j < WSEG0) { src = w0; local = j; }
        else {
            int jj = j - WSEG0;
            int seg = jj / WSEGQ;
            local = jj - seg * WSEGQ;
            const float4* ws[6] = { w1, w2, w3, w4, w5, w6 };
            src = ws[seg];
        }
        dst += j - local ? 0 : 0;   // base handled below
        dst = wh_out + (size_t)(j - local) * 2 / 2 * 0 + 0;  // (placeholder, fixed next line)
        dst = wh_out + (size_t)(j) - local + local;          // = wh_out + j... simplified:
        dst = wh_out;
        local = j;                  // weights are packed contiguously in wh order
        // recompute src/local against packed layout:
        if (j < WSEG0) { src = w0; local = j; }
        else {
            int jj = j - WSEG0;
            int seg = jj / WSEGQ;
            const float4* ws[6] = { w1, w2, w3, w4, w5, w6 };
            src = ws[seg];
            local = jj - seg * WSEGQ;
        }
        float4 v = src[local];
        dst = wh_out + (size_t)j * 2;
        dst[0] = __floats2half2_rn(v.x, v.y);
        dst[1] = __floats2half2_rn(v.z, v.w);
        return;
    }
    float4 v = src[local];
    dst = xh_out + (size_t)local * 2;
    dst[0] = __floats2half2_rn(v.x, v.y);
    dst[1] = __floats2half2_rn(v.z, v.w);
}

// LayerNorm + ReLU; IN16/OUT16 select fp16 input/output
template <int IN16, int OUT16>
__global__ void ln_relu(const void* __restrict__ inv, void* __restrict__ outv,
                        const float* __restrict__ g, const float* __restrict__ b) {
    size_t warp = ((size_t)blockIdx.x * blockDim.x + threadIdx.x) >> 5;
    int lane = threadIdx.x & 31;
    float4 v[4];
    float s = 0.0f, s2 = 0.0f;
#pragma unroll
    for (int c = 0; c < 4; ++c) {
        if (IN16) {
            const __half2* src = (const __half2*)((const __half*)inv + warp * HID);
            float2 a = __half22float2(src[(lane + 32 * c) * 2 + 0]);
            float2 d = __half22float2(src[(lane + 32 * c) * 2 + 1]);
            v[c].x = a.x; v[c].y = a.y; v[c].z = d.x; v[c].w = d.y;
        } else {
            v[c] = ((const float4*)((const float*)inv + warp * HID))[lane + 32 * c];
        }
        s  += v[c].x + v[c].y + v[c].z + v[c].w;
        s2 += v[c].x * v[c].x + v[c].y * v[c].y + v[c].z * v[c].z + v[c].w * v[c].w;
    }
    s = wred(s); s2 = wred(s2);
    float mu = s * (1.0f / HID);
    float var = s2 * (1.0f / HID) - mu * mu;
    float rstd = rsqrtf(var + LN_EPS);
#pragma unroll
    for (int c = 0; c < 4; ++c) {
        int i4 = lane + 32 * c;
        float4 gg = ((const float4*)g)[i4];
        float4 bb = ((const float4*)b)[i4];
        float4 o;
        o.x = fmaxf(0.0f, (v[c].x - mu) * rstd * gg.x + bb.x);
        o.y = fmaxf(0.0f, (v[c].y - mu) * rstd * gg.y + bb.y);
        o.z = fmaxf(0.0f, (v[c].z - mu) * rstd * gg.z + bb.z);
        o.w = fmaxf(0.0f, (v[c].w - mu) * rstd * gg.w + bb.w);
        if (OUT16) {
            __half2* dst = (__half2*)((__half*)outv + warp * HID);
            dst[i4 * 2 + 0] = __floats2half2_rn(o.x, o.y);
            dst[i4 * 2 + 1] = __floats2half2_rn(o.z, o.w);
        } else {
            ((float4*)((float*)outv + warp * HID))[i4] = o;
        }
    }
}

// k (fp16): eps-substitute, L2-normalize, store fp16; 8-row column partials (fp32).
__global__ void norm_k(__half* __restrict__ X, float* __restrict__ Part) {
    __shared__ float sacc[8][HID];
    int w = threadIdx.x >> 5, lane = threadIdx.x & 31;
    size_t row = (size_t)blockIdx.x * 8 + w;
    __half2* p = (__half2*)(X + row * HID);
    float2 f[8];
    float s2 = 0.0f;
#pragma unroll
    for (int c = 0; c < 8; ++c) {
        f[c] = __half22float2(p[lane + 32 * c]);
        if (f[c].x == 0.0f) f[c].x = QK_EPS;
        if (f[c].y == 0.0f) f[c].y = QK_EPS;
        s2 += f[c].x * f[c].x + f[c].y * f[c].y;
    }
    s2 = wred(s2);
    float rn = rsqrtf(s2);
#pragma unroll
    for (int c = 0; c < 8; ++c) {
        f[c].x *= rn; f[c].y *= rn;
        __half2 h2 = __floats2half2_rn(f[c].x, f[c].y);
        p[lane + 32 * c] = h2;
        float2 fq = __half22float2(h2);
        sacc[w][(lane + 32 * c) * 2 + 0] = fq.x;
        sacc[w][(lane + 32 * c) * 2 + 1] = fq.y;
    }
    __syncthreads();
#pragma unroll
    for (int ch = threadIdx.x; ch < HID; ch += 256) {
        float sum = 0.0f;
#pragma unroll
        for (int r = 0; r < 8; ++r) sum += sacc[r][ch];
        Part[(size_t)blockIdx.x * HID + ch] = sum;
    }
}

__global__ void ksum_reduce(const float* __restrict__ Part, float* __restrict__ KS) {
    int idx = blockIdx.x * blockDim.x + threadIdx.x;    // 16*512
    int graph = idx >> 9, ch = idx & 511;
    float s = 0.0f;
    const float* p = Part + ((size_t)graph * 512) * HID + ch;
#pragma unroll 8
    for (int b = 0; b < 512; ++b) s += p[(size_t)b * HID];
    KS[idx] = s;
}

// q (fp16): eps-substitute, normalize, store fp16; den[row] = dot(qn, ks) + N
__global__ void norm_q_den(__half* __restrict__ X, const float* __restrict__ KS,
                           float* __restrict__ den) {
    size_t warp = ((size_t)blockIdx.x * blockDim.x + threadIdx.x) >> 5;
    int lane = threadIdx.x & 31;
    int graph = (int)(warp >> 12);
    __half2* p = (__half2*)(X + warp * HID);
    const float2* kp = (const float2*)(KS + (size_t)graph * HID);
    float2 f[8];
    float s2 = 0.0f;
#pragma unroll
    for (int c = 0; c < 8; ++c) {
        f[c] = __half22float2(p[lane + 32 * c]);
        if (f[c].x == 0.0f) f[c].x = QK_EPS;
        if (f[c].y == 0.0f) f[c].y = QK_EPS;
        s2 += f[c].x * f[c].x + f[c].y * f[c].y;
    }
    s2 = wred(s2);
    float rn = rsqrtf(s2);
    float d = 0.0f;
#pragma unroll
    for (int c = 0; c < 8; ++c) {
        f[c].x *= rn; f[c].y *= rn;
        __half2 h2 = __floats2half2_rn(f[c].x, f[c].y);
        p[lane + 32 * c] = h2;
        float2 fq = __half22float2(h2);
        float2 kk = kp[lane + 32 * c];
        d += fq.x * kk.x + fq.y * kk.y;
    }
    d = wred(d);
    if (lane == 0) den[warp] = d + (float)NNODES;
}

// ================= launch =================
extern "C" void kernel_launch(void* const* d_in, const int* in_sizes, int n_in,
                              void* d_out, int out_size) {
    const float* x     = (const float*)d_in[0];
    const float* fc0_w = (const float*)d_in[1];
    const float* fc0_b = (const float*)d_in[2];
    const float* ln_g[3] = { (const float*)d_in[3], (const float*)d_in[8],  (const float*)d_in[13] };
    const float* ln_b[3] = { (const float*)d_in[4], (const float*)d_in[9],  (const float*)d_in[14] };
    const float* qw[2] = { (const float*)d_in[5],  (const float*)d_in[10] };
    const float* kw[2] = { (const float*)d_in[6],  (const float*)d_in[11] };
    const float* vw[2] = { (const float*)d_in[7],  (const float*)d_in[12] };
    float* out = (float*)d_out;
    // batch = repeat(arange(16), 4096): argsort and rev_perm are identities.

    __half *h, *q, *k, *v, *xh, *wh, *kvsh;
    float *t, *ksp, *ks, *den;
    cudaGetSymbolAddress((void**)&h,    g_h);
    cudaGetSymbolAddress((void**)&q,    g_q);
    cudaGetSymbolAddress((void**)&k,    g_k);
    cudaGetSymbolAddress((void**)&v,    g_v);
    cudaGetSymbolAddress((void**)&xh,   g_xh);
    cudaGetSymbolAddress((void**)&wh,   g_wh);
    cudaGetSymbolAddress((void**)&kvsh, g_kvsh);
    cudaGetSymbolAddress((void**)&t,    g_t);
    cudaGetSymbolAddress((void**)&ksp,  g_ksp);
    cudaGetSymbolAddress((void**)&ks,   g_ks);
    cudaGetSymbolAddress((void**)&den,  g_den);
    __half* th = (__half*)t;            // fp16 view for intermediate pre-LN tensors

    cudaFuncSetAttribute((const void*)mm_tc<0,0,EPI_BIAS,1,0>,
                         cudaFuncAttributeMaxDynamicSharedMemorySize, SMEM_BYTES);
    cudaFuncSetAttribute((const void*)mm_tc<0,0,EPI_NONE,1,1>,
                         cudaFuncAttributeMaxDynamicSharedMemorySize, SMEM_BYTES);
    cudaFuncSetAttribute((const void*)mm_tc<1,1,EPI_NONE,1,0>,
                         cudaFuncAttributeMaxDynamicSharedMemorySize, SMEM_BYTES);
    cudaFuncSetAttribute((const void*)mm_tc<0,1,EPI_ATT,1,0>,
                         cudaFuncAttributeMaxDynamicSharedMemorySize, SMEM_BYTES);
    cudaFuncSetAttribute((const void*)mm_tc<0,1,EPI_ATT,0,0>,
                         cudaFuncAttributeMaxDynamicSharedMemorySize, SMEM_BYTES);

    // fp16 weights: fc0 then per-layer [3*HID, HID] contiguous (q,k,v) — packed order
    __half* wh_fc0 = wh;
    __half* wh_l[2] = { wh + (size_t)HID * INCH,
                        wh + (size_t)HID * INCH + 3 * (size_t)HID * HID };

    // single conversion launch: x + all 7 weights
    cvt_all<<<(CVT_TOTAL + 255) / 256, 256>>>(
        (const float4*)x, (const float4*)fc0_w,
        (const float4*)qw[0], (const float4*)kw[0], (const float4*)vw[0],
        (const float4*)qw[1], (const float4*)kw[1], (const float4*)vw[1],
        (__half2*)xh, (__half2*)wh);

    const int row_blocks = TOTAL / 8;

    // th = fp16(x @ fc0_w^T + b) ; h = fp16(relu(LN(th)))
    mm_tc<0,0,EPI_BIAS,1,0><<<dim3(HID / BN, TOTAL / BM), 256, SMEM_BYTES>>>(
        xh, wh_fc0, th, nullptr, nullptr, nullptr, nullptr, fc0_b,
        INCH, INCH, INCH, HID, 0, 0, 0, 0);
    ln_relu<1,1><<<row_blocks, 256>>>(th, h, ln_g[0], ln_b[0]);

    for (int l = 0; l < 2; ++l) {
        // merged QKV: B = [1536,512] fp16 weights; outputs q/k/v fp16
        mm_tc<0,0,EPI_NONE,1,1><<<dim3(12, TOTAL / BM), 256, SMEM_BYTES>>>(
            h, wh_l[l], q, k, v, nullptr, nullptr, nullptr,
            HID, HID, HID, HID, 0, 0, 0, 0);
        norm_k<<<KBLOCKS, 256>>>(k, ksp);
        ksum_reduce<<<(NGRAPH * HID) / 256, 256>>>(ksp, ks);
        norm_q_den<<<row_blocks, 256>>>(q, ks, den);
        // kvs[g][m,d] = sum_n k[g,n,m] * v[g,n,d]  — single wave (256 CTAs), fp16 out
        mm_tc<1,1,EPI_NONE,1,0><<<dim3(HID / BN, HID / BM, NGRAPH), 256, SMEM_BYTES>>>(
            k, v, kvsh, nullptr, nullptr, nullptr, nullptr, nullptr,
            NNODES, HID, HID, HID,
            (size_t)NNODES * HID, (size_t)NNODES * HID, (size_t)HID * HID, 0);
        // pre-LN attention output: layer0 -> fp16 th ; layer1 -> fp32 t (protect output)
        if (l == 0) {
            mm_tc<0,1,EPI_ATT,1,0><<<dim3(HID / BN, NNODES / BM, NGRAPH), 256, SMEM_BYTES>>>(
                q, kvsh, th, nullptr, nullptr, v, h, den,
                HID, HID, HID, HID, 0, (size_t)HID * HID, 0, NNODES);
            ln_relu<1,1><<<row_blocks, 256>>>(th, h, ln_g[1], ln_b[1]);
        } else {
            mm_tc<0,1,EPI_ATT,0,0><<<dim3(HID / BN, NNODES / BM, NGRAPH), 256, SMEM_BYTES>>>(
                q, kvsh, t, nullptr, nullptr, v, h, den,
                HID, HID, HID, HID, 0, (size_t)HID * HID, 0, NNODES);
            ln_relu<0,0><<<row_blocks, 256>>>(t, out, ln_g[2], ln_b[2]);
        }
    }
}

// round 15
// speedup vs baseline: 1.1875x; 1.0698x over previous
#include <cuda_runtime.h>
#include <cuda_fp16.h>
#include <cstdint>
#include <cstddef>

// ---------------- problem constants ----------------
#define TOTAL    65536          // B_GRAPHS * N_NODES
#define NGRAPH   16
#define NNODES   4096
#define INCH     256
#define HID      512
#define LN_EPS   1e-5f
#define QK_EPS   1e-6f
#define KROWS    32             // rows per norm_k block
#define KBLOCKS  (TOTAL / KROWS)   // 2048

// ---------------- GEMM tiling: 128x128 tile, warp 64x32, fp16, BK=32 ----------------
#define BM 128
#define BN 128
#define BK 32
#define SLOT_BYTES  10240
#define STAGE_BYTES (2 * SLOT_BYTES)
#define NSTAGE 4
#define SMEM_BYTES (NSTAGE * STAGE_BYTES)   // 81920 -> 2 CTAs/SM (160 KB)

// epilogue modes
#define EPI_NONE 0
#define EPI_BIAS 1
#define EPI_ATT  2

// ---------------- scratch (device globals; no allocation) ----------------
__device__ __half g_h  [(size_t)TOTAL * HID];
__device__ __half g_q  [(size_t)TOTAL * HID];
__device__ __half g_k  [(size_t)TOTAL * HID];
__device__ __half g_v  [(size_t)TOTAL * HID];
__device__ __half g_xh [(size_t)TOTAL * INCH];
__device__ __half g_wh [(size_t)(HID * INCH + 6 * HID * HID)];
__device__ __half g_kvsh[(size_t)NGRAPH * HID * HID];
__device__ float  g_t  [(size_t)TOTAL * HID];       // fp32 final layer; fp16 view for intermediates
__device__ float  g_ksp [(size_t)KBLOCKS * HID];
__device__ float  g_ks  [(size_t)NGRAPH * HID];
__device__ float  g_den [(size_t)TOTAL];

// ---------------- helpers ----------------
__device__ __forceinline__ uint32_t smem_to_u32(const void* p) {
    uint32_t a;
    asm("{ .reg .u64 t; cvta.to.shared.u64 t, %1; cvt.u32.u64 %0, t; }" : "=r"(a) : "l"(p));
    return a;
}
__device__ __forceinline__ void mma_f16(float (&c)[4], const uint32_t (&a)[4],
                                        const uint32_t (&b)[2]) {
    asm volatile(
        "mma.sync.aligned.m16n8k16.row.col.f32.f16.f16.f32 "
        "{%0,%1,%2,%3}, {%4,%5,%6,%7}, {%8,%9}, {%0,%1,%2,%3};"
        : "+f"(c[0]), "+f"(c[1]), "+f"(c[2]), "+f"(c[3])
        : "r"(a[0]), "r"(a[1]), "r"(a[2]), "r"(a[3]), "r"(b[0]), "r"(b[1]));
}
__device__ __forceinline__ void ldsm_x4(uint32_t (&r)[4], uint32_t a) {
    asm volatile("ldmatrix.sync.aligned.m8n8.x4.shared.b16 {%0,%1,%2,%3}, [%4];"
        : "=r"(r[0]), "=r"(r[1]), "=r"(r[2]), "=r"(r[3]) : "r"(a));
}
__device__ __forceinline__ void ldsm_x4t(uint32_t (&r)[4], uint32_t a) {
    asm volatile("ldmatrix.sync.aligned.m8n8.x4.trans.shared.b16 {%0,%1,%2,%3}, [%4];"
        : "=r"(r[0]), "=r"(r[1]), "=r"(r[2]), "=r"(r[3]) : "r"(a));
}
__device__ __forceinline__ void cpa16(uint32_t dst, const void* src) {
    asm volatile("cp.async.cg.shared.global [%0], [%1], 16;" :: "r"(dst), "l"(src) : "memory");
}
#define CP_COMMIT() asm volatile("cp.async.commit_group;" ::: "memory")

// ================= fp16 mma.sync GEMM, 128x128 tile, 4-stage, ONE sync/chunk =================
// prefetch issued BETWEEN the two k16 steps (overlaps ks=0 MMAs; ks=0 ldsm unimpeded)
template <int TA, int TB, int EPI, int OUTH, int MULTI>
__global__ __launch_bounds__(256, 2)
void mm_tc(const __half* __restrict__ A, const __half* __restrict__ B,
           void* __restrict__ Cv, void* __restrict__ C1, void* __restrict__ C2,
           const __half* __restrict__ Vh, const __half* __restrict__ Hh,
           const float* __restrict__ Pf,
           int Kdim, int lda, int ldb, int ldc,
           size_t aG, size_t bG, size_t cG, int mZ) {
    extern __shared__ char smem[];
    const uint32_t sb = smem_to_u32(smem);

    const int tid = threadIdx.x;
    const int wid = tid >> 5, lane = tid & 31;
    const int wm = wid & 1, wn = wid >> 1;
    const int tr = lane >> 2, tq = lane & 3;

    const int graph = blockIdx.z;
    A += aG * graph;
    B += bG * graph;
    void* Cp;
    int n0c;
    if (MULTI) {
        void* bufs[3] = { Cv, C1, C2 };
        Cp = bufs[blockIdx.x >> 2];
        n0c = (blockIdx.x & 3) * BN;
    } else {
        Cp = OUTH ? (void*)((__half*)Cv + cG * graph)
                  : (void*)((float*)Cv + cG * graph);
        n0c = blockIdx.x * BN;
    }
    const int m0 = blockIdx.y * BM + mZ * graph;
    const int n0 = blockIdx.x * BN;

    uint32_t aBase, bBase;
    if (TA == 0) aBase = (uint32_t)((wm * 64 + (lane & 15)) * 80 + (lane >> 4) * 16);
    else         aBase = (uint32_t)(((lane >> 4) * 8 + (lane & 7)) * 272
                                    + (wm * 64 + ((lane >> 3) & 1) * 8) * 2);
    if (TB == 0) bBase = (uint32_t)((wn * 32 + (lane >> 4) * 8 + (lane & 7)) * 80
                                    + ((lane >> 3) & 1) * 16);
    else         bBase = (uint32_t)((((lane >> 3) & 1) * 8 + (lane & 7)) * 272
                                    + (wn * 32 + (lane >> 4) * 8) * 2);

    auto issue = [&](int stage, int ktile) {
        const int k0 = ktile * BK;
        uint32_t slotA = sb + (uint32_t)stage * STAGE_BYTES;
        uint32_t slotB = slotA + SLOT_BYTES;
        if (TA == 0) {
            int row = tid >> 1, hb = (tid & 1) * 16;
            const __half* s = A + (size_t)(m0 + row) * lda + k0 + hb;
            uint32_t d = slotA + (uint32_t)(row * 80 + hb * 2);
            cpa16(d, s); cpa16(d + 16, s + 8);
        } else {
            int kr = tid >> 3, c = (tid & 7) * 16;
            const __half* s = A + (size_t)(k0 + kr) * lda + m0 + c;
            uint32_t d = slotA + (uint32_t)(kr * 272 + c * 2);
            cpa16(d, s); cpa16(d + 16, s + 8);
        }
        if (TB == 0) {
            int row = tid >> 1, hb = (tid & 1) * 16;
            const __half* s = B + (size_t)(n0 + row) * ldb + k0 + hb;
            uint32_t d = slotB + (uint32_t)(row * 80 + hb * 2);
            cpa16(d, s); cpa16(d + 16, s + 8);
        } else {
            int kr = tid >> 3, c = (tid & 7) * 16;
            const __half* s = B + (size_t)(k0 + kr) * ldb + n0 + c;
            uint32_t d = slotB + (uint32_t)(kr * 272 + c * 2);
            cpa16(d, s); cpa16(d + 16, s + 8);
        }
    };

    // one k16 compute step
    auto step = [&](uint32_t sA, uint32_t sB, int ks, float (&acc)[4][4][4]) {
        uint32_t afr[4][4], bfr[4][2];
        if (TA == 0) {
#pragma unroll
            for (int mi = 0; mi < 4; ++mi)
                ldsm_x4(afr[mi], sA + aBase + (uint32_t)(mi * 1280 + ks * 32));
        } else {
#pragma unroll
            for (int mi = 0; mi < 4; ++mi)
                ldsm_x4t(afr[mi], sA + aBase + (uint32_t)(mi * 32 + ks * 4352));
        }
        if (TB == 0) {
#pragma unroll
            for (int p = 0; p < 2; ++p) {
                uint32_t t4[4];
                ldsm_x4(t4, sB + bBase + (uint32_t)(p * 1280 + ks * 32));
                bfr[2 * p + 0][0] = t4[0]; bfr[2 * p + 0][1] = t4[1];
                bfr[2 * p + 1][0] = t4[2]; bfr[2 * p + 1][1] = t4[3];
            }
        } else {
#pragma unroll
            for (int p = 0; p < 2; ++p) {
                uint32_t t4[4];
                ldsm_x4t(t4, sB + bBase + (uint32_t)(p * 32 + ks * 4352));
                bfr[2 * p + 0][0] = t4[0]; bfr[2 * p + 0][1] = t4[1];
                bfr[2 * p + 1][0] = t4[2]; bfr[2 * p + 1][1] = t4[3];
            }
        }
#pragma unroll
        for (int mi = 0; mi < 4; ++mi)
#pragma unroll
            for (int ni = 0; ni < 4; ++ni)
                mma_f16(acc[mi][ni], afr[mi], bfr[ni]);
    };

    float acc[4][4][4] = {};

    issue(0, 0); CP_COMMIT();
    issue(1, 1); CP_COMMIT();
    issue(2, 2); CP_COMMIT();

    const int nK = Kdim / BK;
    for (int kt = 0; kt < nK; ++kt) {
        int rem = nK - 1 - kt;
        if (rem >= 2) {
            asm volatile("cp.async.wait_group 2;" ::: "memory");
        } else if (rem == 1) {
            asm volatile("cp.async.wait_group 1;" ::: "memory");
        } else {
            asm volatile("cp.async.wait_group 0;" ::: "memory");
        }
        __syncthreads();    // single barrier: data visibility + slot-reuse protection

        uint32_t sA = sb + (uint32_t)(kt % NSTAGE) * STAGE_BYTES;
        uint32_t sB = sA + SLOT_BYTES;
        step(sA, sB, 0, acc);
        // prefetch 3 chunks ahead MID-compute: slot (kt-1)%4 was consumed last
        // iteration; the barrier above protects the overwrite. Issue overlaps
        // the ks=0 MMAs still in flight.
        if (kt + 3 < nK) { issue((kt + 3) % NSTAGE, kt + 3); CP_COMMIT(); }
        step(sA, sB, 1, acc);
    }

    // ---------------- epilogue ----------------
#pragma unroll
    for (int mi = 0; mi < 4; ++mi) {
        int rbase = m0 + wm * 64 + mi * 16 + tr;
#pragma unroll
        for (int half = 0; half < 2; ++half) {
            size_t row = (size_t)rbase + half * 8;
            float dinv = 0.0f;
            if (EPI == EPI_ATT) dinv = 1.0f / Pf[row];
#pragma unroll
            for (int ni = 0; ni < 4; ++ni) {
                int col = n0c + wn * 32 + ni * 8 + tq * 2;
                float c0 = acc[mi][ni][half * 2 + 0];
                float c1 = acc[mi][ni][half * 2 + 1];
                float2 o;
                if (EPI == EPI_NONE) {
                    o.x = c0; o.y = c1;
                } else if (EPI == EPI_BIAS) {
                    float2 bv = *(const float2*)(Pf + col);
                    o.x = c0 + bv.x; o.y = c1 + bv.y;
                } else {
                    float2 vv = __half22float2(*(const __half2*)(Vh + row * HID + col));
                    float2 hh = __half22float2(*(const __half2*)(Hh + row * HID + col));
                    o.x = ((c0 + 4096.0f * vv.x) * dinv + hh.x) * 0.5f;
                    o.y = ((c1 + 4096.0f * vv.y) * dinv + hh.y) * 0.5f;
                }
                if (OUTH) {
                    *(__half2*)((__half*)Cp + row * (size_t)ldc + col) =
                        __floats2half2_rn(o.x, o.y);
                } else {
                    *(float2*)((float*)Cp + row * (size_t)ldc + col) = o;
                }
            }
        }
    }
}

// ================= elementwise kernels =================
__device__ __forceinline__ float wred(float v) {
#pragma unroll
    for (int o = 16; o; o >>= 1) v += __shfl_xor_sync(0xffffffffu, v, o);
    return v;
}

// single launch converting x AND all 7 weight tensors into fp16 buffers
#define XSEG  (TOTAL * INCH / 4)    // x: 4194304 float4
#define WSEG0 (HID * INCH / 4)      // fc0: 32768 float4
#define WSEGQ (HID * HID / 4)       // each qkv: 65536 float4
#define CVT_TOTAL (XSEG + WSEG0 + 6 * WSEGQ)
__global__ void cvt_all(const float4* __restrict__ xin,
                        const float4* __restrict__ w0,
                        const float4* __restrict__ w1, const float4* __restrict__ w2,
                        const float4* __restrict__ w3, const float4* __restrict__ w4,
                        const float4* __restrict__ w5, const float4* __restrict__ w6,
                        __half2* __restrict__ xh_out, __half2* __restrict__ wh_out) {
    int i = blockIdx.x * blockDim.x + threadIdx.x;
    if (i >= CVT_TOTAL) return;
    if (i < XSEG) {
        float4 v = xin[i];
        xh_out[2 * i + 0] = __floats2half2_rn(v.x, v.y);
        xh_out[2 * i + 1] = __floats2half2_rn(v.z, v.w);
    } else {
        int j = i - XSEG;                  // packed index into wh
        const float4* src;
        int local;
        if (j < WSEG0) { src = w0; local = j; }
        else {
            int jj = j - WSEG0;
            int seg = jj / WSEGQ;
            const float4* ws[6] = { w1, w2, w3, w4, w5, w6 };
            src = ws[seg];
            local = jj - seg * WSEGQ;
        }
        float4 v = src[local];
        wh_out[2 * (size_t)j + 0] = __floats2half2_rn(v.x, v.y);
        wh_out[2 * (size_t)j + 1] = __floats2half2_rn(v.z, v.w);
    }
}

// LayerNorm + ReLU; IN16/OUT16 select fp16 input/output
template <int IN16, int OUT16>
__global__ void ln_relu(const void* __restrict__ inv, void* __restrict__ outv,
                        const float* __restrict__ g, const float* __restrict__ b) {
    size_t warp = ((size_t)blockIdx.x * blockDim.x + threadIdx.x) >> 5;
    int lane = threadIdx.x & 31;
    float4 v[4];
    float s = 0.0f, s2 = 0.0f;
#pragma unroll
    for (int c = 0; c < 4; ++c) {
        if (IN16) {
            const __half2* src = (const __half2*)((const __half*)inv + warp * HID);
            float2 a = __half22float2(src[(lane + 32 * c) * 2 + 0]);
            float2 d = __half22float2(src[(lane + 32 * c) * 2 + 1]);
            v[c].x = a.x; v[c].y = a.y; v[c].z = d.x; v[c].w = d.y;
        } else {
            v[c] = ((const float4*)((const float*)inv + warp * HID))[lane + 32 * c];
        }
        s  += v[c].x + v[c].y + v[c].z + v[c].w;
        s2 += v[c].x * v[c].x + v[c].y * v[c].y + v[c].z * v[c].z + v[c].w * v[c].w;
    }
    s = wred(s); s2 = wred(s2);
    float mu = s * (1.0f / HID);
    float var = s2 * (1.0f / HID) - mu * mu;
    float rstd = rsqrtf(var + LN_EPS);
#pragma unroll
    for (int c = 0; c < 4; ++c) {
        int i4 = lane + 32 * c;
        float4 gg = ((const float4*)g)[i4];
        float4 bb = ((const float4*)b)[i4];
        float4 o;
        o.x = fmaxf(0.0f, (v[c].x - mu) * rstd * gg.x + bb.x);
        o.y = fmaxf(0.0f, (v[c].y - mu) * rstd * gg.y + bb.y);
        o.z = fmaxf(0.0f, (v[c].z - mu) * rstd * gg.z + bb.z);
        o.w = fmaxf(0.0f, (v[c].w - mu) * rstd * gg.w + bb.w);
        if (OUT16) {
            __half2* dst = (__half2*)((__half*)outv + warp * HID);
            dst[i4 * 2 + 0] = __floats2half2_rn(o.x, o.y);
            dst[i4 * 2 + 1] = __floats2half2_rn(o.z, o.w);
        } else {
            ((float4*)((float*)outv + warp * HID))[i4] = o;
        }
    }
}

// k (fp16): eps-substitute, L2-normalize, store fp16; 32-row column partials (fp32).
// Each warp handles 4 consecutive rows, accumulating into its sacc slice.
__global__ void norm_k(__half* __restrict__ X, float* __restrict__ Part) {
    __shared__ float sacc[8][HID];
    int w = threadIdx.x >> 5, lane = threadIdx.x & 31;
#pragma unroll
    for (int c = 0; c < 8; ++c) {
        sacc[w][(lane + 32 * c) * 2 + 0] = 0.0f;
        sacc[w][(lane + 32 * c) * 2 + 1] = 0.0f;
    }
    for (int r = 0; r < 4; ++r) {
        size_t row = (size_t)blockIdx.x * KROWS + w * 4 + r;
        __half2* p = (__half2*)(X + row * HID);
        float2 f[8];
        float s2 = 0.0f;
#pragma unroll
        for (int c = 0; c < 8; ++c) {
            f[c] = __half22float2(p[lane + 32 * c]);
            if (f[c].x == 0.0f) f[c].x = QK_EPS;
            if (f[c].y == 0.0f) f[c].y = QK_EPS;
            s2 += f[c].x * f[c].x + f[c].y * f[c].y;
        }
        s2 = wred(s2);
        float rn = rsqrtf(s2);
#pragma unroll
        for (int c = 0; c < 8; ++c) {
            f[c].x *= rn; f[c].y *= rn;
            __half2 h2 = __floats2half2_rn(f[c].x, f[c].y);
            p[lane + 32 * c] = h2;
            float2 fq = __half22float2(h2);
            sacc[w][(lane + 32 * c) * 2 + 0] += fq.x;
            sacc[w][(lane + 32 * c) * 2 + 1] += fq.y;
        }
    }
    __syncthreads();
#pragma unroll
    for (int ch = threadIdx.x; ch < HID; ch += 256) {
        float sum = 0.0f;
#pragma unroll
        for (int r = 0; r < 8; ++r) sum += sacc[r][ch];
        Part[(size_t)blockIdx.x * HID + ch] = sum;
    }
}

__global__ void ksum_reduce(const float* __restrict__ Part, float* __restrict__ KS) {
    int idx = blockIdx.x * blockDim.x + threadIdx.x;    // 16*512
    int graph = idx >> 9, ch = idx & 511;
    const int per_graph = KBLOCKS / NGRAPH;             // 128
    float s = 0.0f;
    const float* p = Part + ((size_t)graph * per_graph) * HID + ch;
#pragma unroll 8
    for (int b = 0; b < per_graph; ++b) s += p[(size_t)b * HID];
    KS[idx] = s;
}

// q (fp16): eps-substitute, normalize, store fp16; den[row] = dot(qn, ks) + N
__global__ void norm_q_den(__half* __restrict__ X, const float* __restrict__ KS,
                           float* __restrict__ den) {
    size_t warp = ((size_t)blockIdx.x * blockDim.x + threadIdx.x) >> 5;
    int lane = threadIdx.x & 31;
    int graph = (int)(warp >> 12);
    __half2* p = (__half2*)(X + warp * HID);
    const float2* kp = (const float2*)(KS + (size_t)graph * HID);
    float2 f[8];
    float s2 = 0.0f;
#pragma unroll
    for (int c = 0; c < 8; ++c) {
        f[c] = __half22float2(p[lane + 32 * c]);
        if (f[c].x == 0.0f) f[c].x = QK_EPS;
        if (f[c].y == 0.0f) f[c].y = QK_EPS;
        s2 += f[c].x * f[c].x + f[c].y * f[c].y;
    }
    s2 = wred(s2);
    float rn = rsqrtf(s2);
    float d = 0.0f;
#pragma unroll
    for (int c = 0; c < 8; ++c) {
        f[c].x *= rn; f[c].y *= rn;
        __half2 h2 = __floats2half2_rn(f[c].x, f[c].y);
        p[lane + 32 * c] = h2;
        float2 fq = __half22float2(h2);
        float2 kk = kp[lane + 32 * c];
        d += fq.x * kk.x + fq.y * kk.y;
    }
    d = wred(d);
    if (lane == 0) den[warp] = d + (float)NNODES;
}

// ================= launch =================
extern "C" void kernel_launch(void* const* d_in, const int* in_sizes, int n_in,
                              void* d_out, int out_size) {
    const float* x     = (const float*)d_in[0];
    const float* fc0_w = (const float*)d_in[1];
    const float* fc0_b = (const float*)d_in[2];
    const float* ln_g[3] = { (const float*)d_in[3], (const float*)d_in[8],  (const float*)d_in[13] };
    const float* ln_b[3] = { (const float*)d_in[4], (const float*)d_in[9],  (const float*)d_in[14] };
    const float* qw[2] = { (const float*)d_in[5],  (const float*)d_in[10] };
    const float* kw[2] = { (const float*)d_in[6],  (const float*)d_in[11] };
    const float* vw[2] = { (const float*)d_in[7],  (const float*)d_in[12] };
    float* out = (float*)d_out;
    // batch = repeat(arange(16), 4096): argsort and rev_perm are identities.

    __half *h, *q, *k, *v, *xh, *wh, *kvsh;
    float *t, *ksp, *ks, *den;
    cudaGetSymbolAddress((void**)&h,    g_h);
    cudaGetSymbolAddress((void**)&q,    g_q);
    cudaGetSymbolAddress((void**)&k,    g_k);
    cudaGetSymbolAddress((void**)&v,    g_v);
    cudaGetSymbolAddress((void**)&xh,   g_xh);
    cudaGetSymbolAddress((void**)&wh,   g_wh);
    cudaGetSymbolAddress((void**)&kvsh, g_kvsh);
    cudaGetSymbolAddress((void**)&t,    g_t);
    cudaGetSymbolAddress((void**)&ksp,  g_ksp);
    cudaGetSymbolAddress((void**)&ks,   g_ks);
    cudaGetSymbolAddress((void**)&den,  g_den);
    __half* th = (__half*)t;            // fp16 view for intermediate pre-LN tensors

    cudaFuncSetAttribute((const void*)mm_tc<0,0,EPI_BIAS,1,0>,
                         cudaFuncAttributeMaxDynamicSharedMemorySize, SMEM_BYTES);
    cudaFuncSetAttribute((const void*)mm_tc<0,0,EPI_NONE,1,1>,
                         cudaFuncAttributeMaxDynamicSharedMemorySize, SMEM_BYTES);
    cudaFuncSetAttribute((const void*)mm_tc<1,1,EPI_NONE,1,0>,
                         cudaFuncAttributeMaxDynamicSharedMemorySize, SMEM_BYTES);
    cudaFuncSetAttribute((const void*)mm_tc<0,1,EPI_ATT,1,0>,
                         cudaFuncAttributeMaxDynamicSharedMemorySize, SMEM_BYTES);
    cudaFuncSetAttribute((const void*)mm_tc<0,1,EPI_ATT,0,0>,
                         cudaFuncAttributeMaxDynamicSharedMemorySize, SMEM_BYTES);

    // fp16 weights: fc0 then per-layer [3*HID, HID] contiguous (q,k,v) — packed order
    __half* wh_fc0 = wh;
    __half* wh_l[2] = { wh + (size_t)HID * INCH,
                        wh + (size_t)HID * INCH + 3 * (size_t)HID * HID };

    // single conversion launch: x + all 7 weights
    cvt_all<<<(CVT_TOTAL + 255) / 256, 256>>>(
        (const float4*)x, (const float4*)fc0_w,
        (const float4*)qw[0], (const float4*)kw[0], (const float4*)vw[0],
        (const float4*)qw[1], (const float4*)kw[1], (const float4*)vw[1],
        (__half2*)xh, (__half2*)wh);

    const int row_blocks = TOTAL / 8;

    // th = fp16(x @ fc0_w^T + b) ; h = fp16(relu(LN(th)))
    mm_tc<0,0,EPI_BIAS,1,0><<<dim3(HID / BN, TOTAL / BM), 256, SMEM_BYTES>>>(
        xh, wh_fc0, th, nullptr, nullptr, nullptr, nullptr, fc0_b,
        INCH, INCH, INCH, HID, 0, 0, 0, 0);
    ln_relu<1,1><<<row_blocks, 256>>>(th, h, ln_g[0], ln_b[0]);

    for (int l = 0; l < 2; ++l) {
        // merged QKV: B = [1536,512] fp16 weights; outputs q/k/v fp16
        mm_tc<0,0,EPI_NONE,1,1><<<dim3(12, TOTAL / BM), 256, SMEM_BYTES>>>(
            h, wh_l[l], q, k, v, nullptr, nullptr, nullptr,
            HID, HID, HID, HID, 0, 0, 0, 0);
        norm_k<<<KBLOCKS, 256>>>(k, ksp);
        ksum_reduce<<<(NGRAPH * HID) / 256, 256>>>(ksp, ks);
        norm_q_den<<<row_blocks, 256>>>(q, ks, den);
        // kvs[g][m,d] = sum_n k[g,n,m] * v[g,n,d]  — single wave (256 CTAs), fp16 out
        mm_tc<1,1,EPI_NONE,1,0><<<dim3(HID / BN, HID / BM, NGRAPH), 256, SMEM_BYTES>>>(
            k, v, kvsh, nullptr, nullptr, nullptr, nullptr, nullptr,
            NNODES, HID, HID, HID,
            (size_t)NNODES * HID, (size_t)NNODES * HID, (size_t)HID * HID, 0);
        // pre-LN attention output: layer0 -> fp16 th ; layer1 -> fp32 t (protect output)
        if (l == 0) {
            mm_tc<0,1,EPI_ATT,1,0><<<dim3(HID / BN, NNODES / BM, NGRAPH), 256, SMEM_BYTES>>>(
                q, kvsh, th, nullptr, nullptr, v, h, den,
                HID, HID, HID, HID, 0, (size_t)HID * HID, 0, NNODES);
            ln_relu<1,1><<<row_blocks, 256>>>(th, h, ln_g[1], ln_b[1]);
        } else {
            mm_tc<0,1,EPI_ATT,0,0><<<dim3(HID / BN, NNODES / BM, NGRAPH), 256, SMEM_BYTES>>>(
                q, kvsh, t, nullptr, nullptr, v, h, den,
                HID, HID, HID, HID, 0, (size_t)HID * HID, 0, NNODES);
            ln_relu<0,0><<<row_blocks, 256>>>(t, out, ln_g[2], ln_b[2]);
        }
    }
}